// round 9
// baseline (speedup 1.0000x reference)
#include <cuda_runtime.h>
#include <math.h>

#define NN 192
#define TT 20
#define DH 64
#define DE 32
#define DR 32
#define NB 48
#define NTH 512
#define RPB 4
#define TPR 128

// ---- device scratch (no allocations allowed) ----
__device__ float g_h1[NN*DH], g_h2[NN*DH];         // post-LSTM / post-gcn0 h (cross-block)
__device__ float g_B0[NN*DH], g_B1[NN*DH];         // pre B-parts (cross-block)
__device__ float g_b0v[NN], g_b1v[NN];             // pre b scalars (cross-block)
__device__ float g_acc[4], g_v[3];
__device__ unsigned g_bar[2];                      // memset to 0 each launch
// transposed weights (built once at kernel start)
__device__ float g_wihT[DE*256];                   // [e][r]
__device__ float g_whhT[DH*256];                   // [e][r]
__device__ float g_wABT[2*2*64*64];                // [p][part][k][h]
__device__ float g_wneiT[2*64*64];                 // [p][k][h]

__device__ __forceinline__ void gbar(unsigned& sense) {
    __syncthreads();
    if (threadIdx.x == 0) {
        unsigned want = sense + 1u;
        __threadfence();
        unsigned a = atomicAdd(&g_bar[0], 1u);
        if (a == NB - 1u) {
            g_bar[0] = 0u;
            asm volatile("st.release.gpu.u32 [%0], %1;" :: "l"(&g_bar[1]), "r"(want) : "memory");
        } else {
            unsigned v;
            for (;;) {
                asm volatile("ld.acquire.gpu.u32 %0, [%1];" : "=r"(v) : "l"(&g_bar[1]) : "memory");
                if (v >= want) break;
                __nanosleep(32);
            }
        }
    }
    __syncthreads();
    sense += 1u;
}

__device__ __forceinline__ float wsum(float v) {
#pragma unroll
    for (int o = 16; o; o >>= 1) v += __shfl_xor_sync(0xffffffffu, v, o);
    return v;
}
__device__ __forceinline__ float wmax(float v) {
#pragma unroll
    for (int o = 16; o; o >>= 1) v = fmaxf(v, __shfl_xor_sync(0xffffffffu, v, o));
    return v;
}

__global__ void __launch_bounds__(NTH, 1)
fused_kernel(const float* __restrict__ abs_, const float* __restrict__ norm,
             const float* __restrict__ w_in, const float* __restrict__ b_in,
             const float* __restrict__ w_ih, const float* __restrict__ w_hh,
             const float* __restrict__ b_ih, const float* __restrict__ b_hh,
             const float* __restrict__ w_rel, const float* __restrict__ b_rel,
             const float* __restrict__ w_gate, const float* __restrict__ b_gate,
             const float* __restrict__ w_ar, const float* __restrict__ b_ar,
             const float* __restrict__ w_nei, const float* __restrict__ w_out,
             const float* __restrict__ b_out,
             const int* __restrict__ seq, const int* __restrict__ nei,
             float* __restrict__ out)
{
    // ---- shared state (persistent across the whole scan) ----
    __shared__ float s_wgT[2*DR*DH];          // [p][k][h] Wg[:, :32]^T
    __shared__ __align__(16) float4 s_cst4[2*DR];  // {wrel_x,wrel_y,brel,war_k}
    __shared__ float s_war[2*2*DH];           // [p][part][k] w_ar slices
    __shared__ float s_bcomb[256];            // b_ih + b_hh
    __shared__ float s_bg[2*DH];              // b_gate
    __shared__ float s_bar2[2];               // b_ar
    __shared__ float s_abs[2*NN];             // abs[t] prefetch
    __shared__ unsigned char s_seqb[NN];      // seq[t] > 0
    __shared__ unsigned char s_neib[RPB][NN]; // nei[t,i,:] > 0
    __shared__ float s_gates[RPB][256];       // LSTM gates / msgf scratch
    __shared__ float s_xh[RPB][96];
    __shared__ float s_pos[RPB][NN];
    __shared__ unsigned char s_actb[RPB][NN];
    __shared__ float s_msgM[RPB][4][DH];
    __shared__ float s_hn[RPB][DH];
    __shared__ float s_A[RPB][DH];
    __shared__ float s_a[RPB];
    __shared__ float s_rr[RPB][16];
    __shared__ float s_v1[RPB][4];
    __shared__ float s_h[RPB][DH], s_c[RPB][DH];
    __shared__ float s_og[RPB][DH], s_ctmp[RPB][DH];
    __shared__ int   s_cnt[RPB];

    const int tid  = threadIdx.x;
    const int g    = tid >> 7;            // row group 0..3
    const int ltid = tid & 127;           // 0..127 within group
    const int lane = tid & 31;
    const int w4   = (tid >> 5) & 3;      // warp within group
    const int i    = blockIdx.x * RPB + g;
    const int gtid = blockIdx.x * NTH + tid;
    unsigned sense = 0;

    // ---- one-time smem constant loads ----
    for (int idx = tid; idx < 2*DR*DH; idx += NTH) {
        int p = idx >> 11, r = idx & 2047, k = r >> 6, h = r & 63;
        s_wgT[idx] = w_gate[p*DH*160 + h*160 + k];
    }
    for (int idx = tid; idx < 2*DR; idx += NTH) {
        int p = idx >> 5, k = idx & 31;
        s_cst4[idx] = make_float4(w_rel[p*DR*2 + k*2 + 0], w_rel[p*DR*2 + k*2 + 1],
                                  b_rel[p*DR + k],          w_ar[p*160 + k]);
    }
    for (int idx = tid; idx < 2*2*DH; idx += NTH) {
        int p = idx >> 7, part = (idx >> 6) & 1, k = idx & 63;
        s_war[idx] = w_ar[p*160 + 32 + part*64 + k];
    }
    if (tid < 256) s_bcomb[tid] = b_ih[tid] + b_hh[tid];
    if (tid < 2*DH) s_bg[tid] = b_gate[tid];
    if (tid < 2) s_bar2[tid] = b_ar[tid];
    if (ltid < DH) { s_h[g][ltid] = 0.f; s_c[g][ltid] = 0.f; }

    // ---- one-time global transposes + zero init ----
    for (int idx = gtid; idx < DE*256; idx += NB*NTH) {
        int e = idx >> 8, r = idx & 255;
        g_wihT[idx] = w_ih[r*DE + e];
    }
    for (int idx = gtid; idx < DH*256; idx += NB*NTH) {
        int e = idx >> 8, r = idx & 255;
        g_whhT[idx] = w_hh[r*DH + e];
    }
    for (int idx = gtid; idx < 2*2*64*64; idx += NB*NTH) {
        int h = idx & 63, k = (idx >> 6) & 63, part = (idx >> 12) & 1, p = idx >> 13;
        g_wABT[idx] = w_gate[p*DH*160 + h*160 + 32 + part*64 + k];
    }
    for (int idx = gtid; idx < 2*64*64; idx += NB*NTH) {
        int h = idx & 63, k = (idx >> 6) & 63, p = idx >> 12;
        g_wneiT[idx] = w_nei[p*DH*DH + h*DH + k];
    }
    if (gtid < NN*2) out[(TT-1)*NN*2 + gtid] = 0.f;
    if (blockIdx.x == 0 && tid < 4) g_acc[tid] = 0.f;
    if (blockIdx.x == 0 && tid < 3) g_v[tid] = 0.f;
    gbar(sense);

    for (int t = 0; t < TT-1; t++) {
        //================ Phase A: prefetch + LSTM + pre0 ================
        if (tid < 2*NN) s_abs[tid] = abs_[t*NN*2 + tid];
        if (tid < NN)   s_seqb[tid] = (unsigned char)(seq[t*NN + tid] > 0);
        for (int jj = ltid; jj < NN; jj += TPR)
            s_neib[g][jj] = (unsigned char)(nei[(size_t)t*NN*NN + (size_t)i*NN + jj] > 0);
        if (ltid < DE) {
            float n0 = norm[(t*NN + i)*2 + 0];
            float n1 = norm[(t*NN + i)*2 + 1];
            s_xh[g][ltid] = fmaxf(n0*w_in[ltid*2 + 0] + n1*w_in[ltid*2 + 1] + b_in[ltid], 0.f);
        }
        if (ltid < DH) s_xh[g][32 + ltid] = s_h[g][ltid];
        __syncthreads();
        {
            int r0 = ltid, r1 = ltid + 128;
            float a0 = s_bcomb[r0], a1 = s_bcomb[r1];
#pragma unroll
            for (int e = 0; e < DE; e++) {
                float x = s_xh[g][e];
                a0 += x * g_wihT[e*256 + r0];
                a1 += x * g_wihT[e*256 + r1];
            }
#pragma unroll
            for (int e = 0; e < DH; e++) {
                float x = s_xh[g][32 + e];
                a0 += x * g_whhT[e*256 + r0];
                a1 += x * g_whhT[e*256 + r1];
            }
            s_gates[g][r0] = a0;
            s_gates[g][r1] = a1;
        }
        __syncthreads();
        if (ltid < DH) {
            int h = ltid;
            float ig = 1.f/(1.f+__expf(-s_gates[g][h]));
            float fg = 1.f/(1.f+__expf(-s_gates[g][64 + h]));
            float gg = tanhf(s_gates[g][128 + h]);
            float og = 1.f/(1.f+__expf(-s_gates[g][192 + h]));
            float c1 = fg*s_c[g][h] + ig*gg;
            float h1 = og*tanhf(c1);
            s_ctmp[g][h] = c1;
            s_og[g][h] = og;
            s_hn[g][h] = h1;
            g_h1[i*DH + h] = h1;
        }
        __syncthreads();
        {   // pre0: A-part -> smem, B-part -> global
            int h = ltid & 63, part = ltid >> 6;
            const float* wp = g_wABT + (part*64)*64;   // stage 0
            float acc = 0.f;
#pragma unroll
            for (int k = 0; k < DH; k++) acc += s_hn[g][k]*wp[k*64 + h];
            if (part == 0) s_A[g][h] = acc; else g_B0[i*DH + h] = acc;
        }
        if (w4 == 0) {
            float pa = s_hn[g][lane]*s_war[lane] + s_hn[g][32+lane]*s_war[32+lane];
            pa = wsum(pa);
            if (lane == 0) s_a[g] = pa;
        } else if (w4 == 1) {
            float pb = s_hn[g][lane]*s_war[64+lane] + s_hn[g][32+lane]*s_war[96+lane];
            pb = wsum(pb);
            if (lane == 0) g_b0v[i] = pb;
        }
        gbar(sense);

        //================ Phases B (stage0) and C (stage1) ================
#pragma unroll 1
        for (int STAGE = 0; STAGE < 2; STAGE++) {
            if (STAGE == 1 && blockIdx.x == 0 && tid == 0) {
                const float eps = 1e-6f;
                g_v[0] += g_acc[0] / (g_acc[1]*(float)DH + eps);
                g_v[1] += g_acc[2] / (g_acc[3] + eps);
                g_v[2] += g_acc[1] / (float)NN;
                g_acc[0] = g_acc[1] = g_acc[2] = g_acc[3] = 0.f;
            }
            const float* hcur = STAGE ? g_h2 : g_h1;
            const float* gB   = STAGE ? g_B1 : g_B0;
            const float* gbv  = STAGE ? g_b1v : g_b0v;
            const float barv  = s_bar2[STAGE];
            const float aI    = s_a[g];
            const int   mi    = s_seqb[i];
            const float ax = s_abs[2*i], ay = s_abs[2*i+1];
            const float4* cst = s_cst4 + STAGE*DR;

            if (ltid == 0) s_cnt[g] = 0;
            // entry: scores for j1 = ltid, j2 = 128+ltid (ltid<64)
            const bool has2 = ltid < 64;
            int j1 = ltid, j2 = 128 + ltid;
            float nf1, nf2 = 0.f, sc1, sc2 = -1e30f;
            float cx1, cy1, cx2 = 0.f, cy2 = 0.f;
            {
                nf1 = (s_neib[g][j1] && mi && s_seqb[j1]) ? 1.f : 0.f;
                cx1 = ax - s_abs[2*j1]; cy1 = ay - s_abs[2*j1+1];
                float sc = 0.f;
#pragma unroll
                for (int k = 0; k < DR; k++) {
                    float4 c4 = cst[k];
                    float rv = fmaxf(fmaf(cx1, c4.x, fmaf(cy1, c4.y, c4.z)), 0.f);
                    sc += rv * c4.w;
                }
                sc += aI + __ldcg(&gbv[j1]) + barv;
                sc1 = (nf1 > 0.f) ? sc : -1e9f;
            }
            if (has2) {
                nf2 = (s_neib[g][j2] && mi && s_seqb[j2]) ? 1.f : 0.f;
                cx2 = ax - s_abs[2*j2]; cy2 = ay - s_abs[2*j2+1];
                float sc = 0.f;
#pragma unroll
                for (int k = 0; k < DR; k++) {
                    float4 c4 = cst[k];
                    float rv = fmaxf(fmaf(cx2, c4.x, fmaf(cy2, c4.y, c4.z)), 0.f);
                    sc += rv * c4.w;
                }
                sc += aI + __ldcg(&gbv[j2]) + barv;
                sc2 = (nf2 > 0.f) ? sc : -1e9f;
            }
            // reduce 1: max score, sum neif
            {
                float m = wmax(fmaxf(sc1, sc2));
                float sn = wsum(nf1 + nf2);
                if (lane == 0) { s_rr[g][w4] = m; s_rr[g][4 + w4] = sn; }
            }
            __syncthreads();
            float mm = fmaxf(fmaxf(s_rr[g][0], s_rr[g][1]), fmaxf(s_rr[g][2], s_rr[g][3]));
            float neiRow = s_rr[g][4] + s_rr[g][5] + s_rr[g][6] + s_rr[g][7];
            float e1 = __expf(sc1 - mm);
            float e2 = has2 ? __expf(sc2 - mm) : 0.f;
            // reduce 2: sum e, max e*neif
            {
                float se = wsum(e1 + e2);
                float mn = wmax(fmaxf(e1*nf1, e2*nf2));
                if (lane == 0) { s_rr[g][8 + w4] = se; s_rr[g][12 + w4] = mn; }
            }
            __syncthreads();
            float inv = 1.f / (s_rr[g][8] + s_rr[g][9] + s_rr[g][10] + s_rr[g][11]);
            float maxposRow = fmaxf(fmaxf(s_rr[g][12], s_rr[g][13]),
                                    fmaxf(s_rr[g][14], s_rr[g][15])) * inv;
            s_pos[g][j1] = e1 * inv * nf1;
            if (has2) s_pos[g][j2] = e2 * inv * nf2;
            // active-list compaction (ballot)
            {
                unsigned b1 = __ballot_sync(0xffffffffu, nf1 > 0.f);
                int base = 0;
                if (lane == 0) base = atomicAdd(&s_cnt[g], __popc(b1));
                base = __shfl_sync(0xffffffffu, base, 0);
                if (nf1 > 0.f) s_actb[g][base + __popc(b1 & ((1u << lane) - 1u))] = (unsigned char)j1;
                if (w4 < 2) {
                    unsigned b2 = __ballot_sync(0xffffffffu, nf2 > 0.f);
                    int base2 = 0;
                    if (lane == 0) base2 = atomicAdd(&s_cnt[g], __popc(b2));
                    base2 = __shfl_sync(0xffffffffu, base2, 0);
                    if (nf2 > 0.f) s_actb[g][base2 + __popc(b2 & ((1u << lane) - 1u))] = (unsigned char)j2;
                }
            }
            __syncthreads();
            // gate + message loop over active neighbors
            const float Ai0 = s_A[g][lane]      + s_bg[STAGE*DH + lane];
            const float Ai1 = s_A[g][32 + lane] + s_bg[STAGE*DH + 32 + lane];
            const float* wgS = s_wgT + STAGE*DR*DH;
            float msg0 = 0.f, msg1 = 0.f, v1p = 0.f;
            int cnt = s_cnt[g];
            for (int a = w4; a < cnt; a += 4) {
                int j = s_actb[g][a];
                float pj = s_pos[g][j];
                float cx = ax - s_abs[2*j], cy = ay - s_abs[2*j+1];
                float acc0 = Ai0 + __ldcg(&gB[j*DH + lane]);
                float acc1 = Ai1 + __ldcg(&gB[j*DH + 32 + lane]);
                float hj0 = __ldcg(&hcur[j*DH + lane]);
                float hj1 = __ldcg(&hcur[j*DH + 32 + lane]);
#pragma unroll
                for (int k = 0; k < DR; k++) {
                    float4 c4 = cst[k];
                    float rv = fmaxf(fmaf(cx, c4.x, fmaf(cy, c4.y, c4.z)), 0.f);
                    acc0 += rv * wgS[k*DH + lane];
                    acc1 += rv * wgS[k*DH + 32 + lane];
                }
                float g0 = 1.f/(1.f+__expf(-acc0));
                float g1 = 1.f/(1.f+__expf(-acc1));
                msg0 += pj*g0*hj0;
                msg1 += pj*g1*hj1;
                v1p  += g0 + g1;
            }
            s_msgM[g][w4][lane]      = msg0;
            s_msgM[g][w4][32 + lane] = msg1;
            v1p = wsum(v1p);
            if (lane == 0) s_v1[g][w4] = v1p;
            __syncthreads();
            if (ltid < DH)
                s_gates[g][ltid] = s_msgM[g][0][ltid] + s_msgM[g][1][ltid]
                                 + s_msgM[g][2][ltid] + s_msgM[g][3][ltid];
            __syncthreads();
            if (ltid < DH) {
                int h = ltid;
                float cn = s_ctmp[g][h];
                const float* wn = g_wneiT + STAGE*DH*DH;
#pragma unroll
                for (int k = 0; k < DH; k++) cn += s_gates[g][k]*wn[k*DH + h];
                float hn = s_og[g][h]*tanhf(cn);
                s_hn[g][h] = hn;
                if (STAGE == 0) {
                    s_ctmp[g][h] = cn;
                    g_h2[i*DH + h] = hn;
                } else if (mi) {
                    s_h[g][h] = hn; s_c[g][h] = cn;
                }
            }
            __syncthreads();
            if (STAGE == 0) {
                {   // pre1
                    int h = ltid & 63, part = ltid >> 6;
                    const float* wp = g_wABT + ((2 + part)*64)*64;  // stage 1
                    float acc = 0.f;
#pragma unroll
                    for (int k = 0; k < DH; k++) acc += s_hn[g][k]*wp[k*64 + h];
                    if (part == 0) s_A[g][h] = acc; else g_B1[i*DH + h] = acc;
                }
                if (w4 == 0) {
                    float pa = s_hn[g][lane]*s_war[128+lane] + s_hn[g][32+lane]*s_war[160+lane];
                    pa = wsum(pa);
                    if (lane == 0) s_a[g] = pa;
                } else if (w4 == 1) {
                    float pb = s_hn[g][lane]*s_war[192+lane] + s_hn[g][32+lane]*s_war[224+lane];
                    pb = wsum(pb);
                    if (lane == 0) g_b1v[i] = pb;
                }
                if (ltid == 0) {
                    float gateSum = s_v1[g][0] + s_v1[g][1] + s_v1[g][2] + s_v1[g][3];
                    atomicAdd(&g_acc[0], gateSum);
                    atomicAdd(&g_acc[1], neiRow);
                    atomicAdd(&g_acc[2], maxposRow);
                    atomicAdd(&g_acc[3], neiRow > 0.f ? 1.f : 0.f);
                }
                gbar(sense);
            } else {
                if (ltid < 2) {
                    float o = b_out[ltid];
#pragma unroll
                    for (int k = 0; k < DH; k++) o += s_hn[g][k]*w_out[ltid*DH + k];
                    out[(t*NN + i)*2 + ltid] = mi ? o : 0.f;
                }
            }
        }
        // no barrier between C and next A (A touches only own-row state)
    }

    // final writeback (own rows, own smem)
    const int OFF = TT*NN*2;
    if (ltid < DH) {
        out[OFF + i*DH + ltid]         = s_h[g][ltid];
        out[OFF + NN*DH + i*DH + ltid] = s_c[g][ltid];
    }
    if (blockIdx.x == 0 && tid < 3) out[OFF + 2*NN*DH + tid] = g_v[tid] / (float)TT;
}

extern "C" void kernel_launch(void* const* d_in, const int* in_sizes, int n_in,
                              void* d_out, int out_size) {
    const float* abs_   = (const float*)d_in[0];
    const float* norm   = (const float*)d_in[1];
    const float* w_in   = (const float*)d_in[3];
    const float* b_in   = (const float*)d_in[4];
    const float* w_ih   = (const float*)d_in[5];
    const float* w_hh   = (const float*)d_in[6];
    const float* b_ih   = (const float*)d_in[7];
    const float* b_hh   = (const float*)d_in[8];
    const float* w_rel  = (const float*)d_in[9];
    const float* b_rel  = (const float*)d_in[10];
    const float* w_gate = (const float*)d_in[11];
    const float* b_gate = (const float*)d_in[12];
    const float* w_ar   = (const float*)d_in[13];
    const float* b_ar   = (const float*)d_in[14];
    const float* w_nei  = (const float*)d_in[15];
    const float* w_out  = (const float*)d_in[16];
    const float* b_out  = (const float*)d_in[17];
    const int*   seq    = (const int*)d_in[18];
    const int*   nei    = (const int*)d_in[19];
    float* out = (float*)d_out;

    void* barptr = nullptr;
    cudaGetSymbolAddress(&barptr, g_bar);
    cudaMemsetAsync(barptr, 0, 2*sizeof(unsigned), 0);

    fused_kernel<<<NB, NTH>>>(abs_, norm, w_in, b_in, w_ih, w_hh, b_ih, b_hh,
                              w_rel, b_rel, w_gate, b_gate, w_ar, b_ar,
                              w_nei, w_out, b_out, seq, nei, out);
}

// round 10
// speedup vs baseline: 1.5817x; 1.5817x over previous
#include <cuda_runtime.h>
#include <math.h>

#define NN 192
#define TT 20
#define DH 64
#define DE 32
#define DR 32
#define NB 96
#define NTH 512
#define RPB 2

// ---- device scratch (no allocations allowed) ----
__device__ float2 g_h1p[NN*32], g_h2p[NN*32];      // packed {h[l], h[l+32]}
__device__ float2 g_B0p[NN*32], g_B1p[NN*32];      // packed pre-B parts
__device__ float  g_b0v[NN], g_b1v[NN];
__device__ float  g_acc[4], g_v[3];
__device__ unsigned g_bar[2];                      // memset to 0 each launch
// transposed weights (built once)
__device__ float g_wihT[DE*256];                   // [e][r]
__device__ float g_whhT[DH*256];                   // [e][r]
__device__ float g_wABT[2*2*64*64];                // [p][part][k][h]
__device__ float g_wneiT[2*64*64];                 // [p][k][h]

__device__ __forceinline__ void gbar(unsigned& sense) {
    __syncthreads();
    if (threadIdx.x == 0) {
        unsigned want = sense + 1u;
        __threadfence();
        unsigned a = atomicAdd(&g_bar[0], 1u);
        if (a == NB - 1u) {
            g_bar[0] = 0u;
            asm volatile("st.release.gpu.u32 [%0], %1;" :: "l"(&g_bar[1]), "r"(want) : "memory");
        } else {
            unsigned v;
            for (;;) {
                asm volatile("ld.acquire.gpu.u32 %0, [%1];" : "=r"(v) : "l"(&g_bar[1]) : "memory");
                if (v >= want) break;
                __nanosleep(32);
            }
        }
    }
    __syncthreads();
    sense += 1u;
}

__device__ __forceinline__ float wsum(float v) {
#pragma unroll
    for (int o = 16; o; o >>= 1) v += __shfl_xor_sync(0xffffffffu, v, o);
    return v;
}
__device__ __forceinline__ float wmax(float v) {
#pragma unroll
    for (int o = 16; o; o >>= 1) v = fmaxf(v, __shfl_xor_sync(0xffffffffu, v, o));
    return v;
}

__global__ void __launch_bounds__(NTH, 1)
fused_kernel(const float* __restrict__ abs_, const float* __restrict__ norm,
             const float* __restrict__ w_in, const float* __restrict__ b_in,
             const float* __restrict__ w_ih, const float* __restrict__ w_hh,
             const float* __restrict__ b_ih, const float* __restrict__ b_hh,
             const float* __restrict__ w_rel, const float* __restrict__ b_rel,
             const float* __restrict__ w_gate, const float* __restrict__ b_gate,
             const float* __restrict__ w_ar, const float* __restrict__ b_ar,
             const float* __restrict__ w_nei, const float* __restrict__ w_out,
             const float* __restrict__ b_out,
             const int* __restrict__ seq, const int* __restrict__ nei,
             float* __restrict__ out)
{
    __shared__ float2 s_wg2[2*DR*32];          // [p][k][lane]{h,h+32}  16KB
    __shared__ __align__(16) float4 s_cst4[2*DR];
    __shared__ float s_war[256];
    __shared__ float s_bcomb[256];
    __shared__ float s_bg[2*DH];
    __shared__ float s_bar2[2];
    __shared__ float s_abs[2*NN];
    __shared__ unsigned char s_seqb[NN];
    __shared__ unsigned char s_neib[RPB][NN];
    __shared__ float s_gates[RPB][256];         // LSTM gates / B scratch
    __shared__ float s_xh[RPB][96];
    __shared__ float s_pos[RPB][NN];
    __shared__ unsigned char s_actb[RPB][NN];
    __shared__ float2 s_msg2[RPB][8][32];
    __shared__ float s_hn[RPB][DH];
    __shared__ float s_A[RPB][DH];
    __shared__ float s_a[RPB];
    __shared__ float s_rr[RPB][32];
    __shared__ float s_v1[RPB][8];
    __shared__ float s_h[RPB][DH], s_c[RPB][DH];
    __shared__ float s_og[RPB][DH], s_ctmp[RPB][DH];
    __shared__ float s_msgf[RPB][DH];
    __shared__ int   s_cnt[RPB];

    const int tid  = threadIdx.x;
    const int g    = tid >> 8;            // row group 0..1
    const int ltid = tid & 255;           // 0..255 within group
    const int lane = tid & 31;
    const int w8   = (tid >> 5) & 7;      // warp within group 0..7
    const int i    = blockIdx.x * RPB + g;
    const int gtid = blockIdx.x * NTH + tid;
    unsigned sense = 0;

    // ---- one-time smem constant loads ----
    for (int idx = tid; idx < 2*DR*32; idx += NTH) {
        int p = idx >> 10, rem = idx & 1023, k = rem >> 5, l = rem & 31;
        s_wg2[idx] = make_float2(w_gate[p*DH*160 + l*160 + k],
                                 w_gate[p*DH*160 + (l+32)*160 + k]);
    }
    for (int idx = tid; idx < 2*DR; idx += NTH) {
        int p = idx >> 5, k = idx & 31;
        s_cst4[idx] = make_float4(w_rel[p*DR*2 + k*2 + 0], w_rel[p*DR*2 + k*2 + 1],
                                  b_rel[p*DR + k],          w_ar[p*160 + k]);
    }
    for (int idx = tid; idx < 256; idx += NTH) {
        int p = idx >> 7, part = (idx >> 6) & 1, k = idx & 63;
        s_war[idx] = w_ar[p*160 + 32 + part*64 + k];
    }
    if (tid < 256) s_bcomb[tid] = b_ih[tid] + b_hh[tid];
    if (tid < 2*DH) s_bg[tid] = b_gate[tid];
    if (tid < 2) s_bar2[tid] = b_ar[tid];
    if (ltid < DH) { s_h[g][ltid] = 0.f; s_c[g][ltid] = 0.f; }

    // ---- one-time global transposes + zero init ----
    for (int idx = gtid; idx < DE*256; idx += NB*NTH) {
        int e = idx >> 8, r = idx & 255;
        g_wihT[idx] = w_ih[r*DE + e];
    }
    for (int idx = gtid; idx < DH*256; idx += NB*NTH) {
        int e = idx >> 8, r = idx & 255;
        g_whhT[idx] = w_hh[r*DH + e];
    }
    for (int idx = gtid; idx < 2*2*64*64; idx += NB*NTH) {
        int h = idx & 63, k = (idx >> 6) & 63, part = (idx >> 12) & 1, p = idx >> 13;
        g_wABT[idx] = w_gate[p*DH*160 + h*160 + 32 + part*64 + k];
    }
    for (int idx = gtid; idx < 2*64*64; idx += NB*NTH) {
        int h = idx & 63, k = (idx >> 6) & 63, p = idx >> 12;
        g_wneiT[idx] = w_nei[p*DH*DH + h*DH + k];
    }
    if (gtid < NN*2) out[(TT-1)*NN*2 + gtid] = 0.f;
    if (blockIdx.x == 0 && tid < 4) g_acc[tid] = 0.f;
    if (blockIdx.x == 0 && tid < 3) g_v[tid] = 0.f;
    gbar(sense);

    for (int t = 0; t < TT-1; t++) {
        //================ Phase A: prefetch + LSTM + pre0 ================
        if (tid < 2*NN) s_abs[tid] = abs_[t*NN*2 + tid];
        if (tid < NN)   s_seqb[tid] = (unsigned char)(seq[t*NN + tid] > 0);
        if (ltid < NN)  s_neib[g][ltid] =
            (unsigned char)(nei[(size_t)t*NN*NN + (size_t)i*NN + ltid] > 0);
        if (ltid < DE) {
            float n0 = norm[(t*NN + i)*2 + 0];
            float n1 = norm[(t*NN + i)*2 + 1];
            s_xh[g][ltid] = fmaxf(n0*w_in[ltid*2 + 0] + n1*w_in[ltid*2 + 1] + b_in[ltid], 0.f);
        }
        if (ltid >= 64 && ltid < 128) s_xh[g][32 + (ltid - 64)] = s_h[g][ltid - 64];
        __syncthreads();
        const int mi = s_seqb[i];
        {   // one gate output per thread
            int r = ltid;
            float a = s_bcomb[r];
#pragma unroll
            for (int e = 0; e < DE; e++) a += s_xh[g][e] * g_wihT[e*256 + r];
#pragma unroll
            for (int e = 0; e < DH; e++) a += s_xh[g][32 + e] * g_whhT[e*256 + r];
            s_gates[g][r] = a;
        }
        __syncthreads();
        if (ltid < DH) {
            int h = ltid;
            float ig = 1.f/(1.f+__expf(-s_gates[g][h]));
            float fg = 1.f/(1.f+__expf(-s_gates[g][64 + h]));
            float gg = tanhf(s_gates[g][128 + h]);
            float og = 1.f/(1.f+__expf(-s_gates[g][192 + h]));
            float c1 = fg*s_c[g][h] + ig*gg;
            float h1 = og*tanhf(c1);
            s_ctmp[g][h] = c1;
            s_og[g][h] = og;
            s_hn[g][h] = h1;
        }
        __syncthreads();
        if (mi) {   // pre0 (results unread when mi==0)
            if (w8 < 2) {            // A[h] -> s_A
                int h = ltid;
                const float* wp = g_wABT;               // stage0, part A
                float acc = 0.f;
#pragma unroll
                for (int k = 0; k < DH; k++) acc += s_hn[g][k]*wp[k*64 + h];
                s_A[g][h] = acc;
            } else if (w8 < 4) {     // B[h] -> scratch
                int h = ltid - 64;
                const float* wp = g_wABT + 64*64;       // stage0, part B
                float acc = 0.f;
#pragma unroll
                for (int k = 0; k < DH; k++) acc += s_hn[g][k]*wp[k*64 + h];
                s_gates[g][h] = acc;
            } else if (w8 == 4) {
                float pa = s_hn[g][lane]*s_war[lane] + s_hn[g][32+lane]*s_war[32+lane];
                pa = wsum(pa);
                if (lane == 0) s_a[g] = pa;
            } else if (w8 == 5) {
                float pb = s_hn[g][lane]*s_war[64+lane] + s_hn[g][32+lane]*s_war[96+lane];
                pb = wsum(pb);
                if (lane == 0) g_b0v[i] = pb;
            } else if (w8 == 6) {
                g_h1p[i*32 + lane] = make_float2(s_hn[g][lane], s_hn[g][32 + lane]);
            }
        }
        __syncthreads();
        if (mi && w8 == 7)
            g_B0p[i*32 + lane] = make_float2(s_gates[g][lane], s_gates[g][lane + 32]);
        gbar(sense);

        //================ Phases B (stage0) and C (stage1) ================
#pragma unroll 1
        for (int STAGE = 0; STAGE < 2; STAGE++) {
            if (STAGE == 1 && blockIdx.x == 0 && tid == 0) {
                const float eps = 1e-6f;
                g_v[0] += g_acc[0] / (g_acc[1]*(float)DH + eps);
                g_v[1] += g_acc[2] / (g_acc[3] + eps);
                g_v[2] += g_acc[1] / (float)NN;
                g_acc[0] = g_acc[1] = g_acc[2] = g_acc[3] = 0.f;
            }
            const float2* hp  = STAGE ? g_h2p : g_h1p;
            const float2* gBp = STAGE ? g_B1p : g_B0p;
            const float*  gbv = STAGE ? g_b1v : g_b0v;
            const float   barv = s_bar2[STAGE];
            const float   aI   = s_a[g];
            const float   ax = s_abs[2*i], ay = s_abs[2*i+1];
            const float4* cst = s_cst4 + STAGE*DR;

            if (ltid == 0) s_cnt[g] = 0;
            // scores: one j per thread
            float nf1 = 0.f, sc1 = -1e30f;
            const int j1 = ltid;
            if (mi && j1 < NN) {
                nf1 = (s_neib[g][j1] && s_seqb[j1]) ? 1.f : 0.f;
                float cx = ax - s_abs[2*j1], cy = ay - s_abs[2*j1+1];
                float sc = 0.f;
#pragma unroll
                for (int k = 0; k < DR; k++) {
                    float4 c4 = cst[k];
                    sc += fmaxf(fmaf(cx, c4.x, fmaf(cy, c4.y, c4.z)), 0.f) * c4.w;
                }
                sc += aI + __ldcg(&gbv[j1]) + barv;
                sc1 = (nf1 > 0.f) ? sc : -1e9f;
            }
            {   // reduce1: max score, sum neif
                float m = wmax(sc1), sn = wsum(nf1);
                if (lane == 0) { s_rr[g][w8] = m; s_rr[g][8 + w8] = sn; }
            }
            __syncthreads();
            float mm = s_rr[g][0], neiRow = s_rr[g][8];
#pragma unroll
            for (int w = 1; w < 8; w++) { mm = fmaxf(mm, s_rr[g][w]); neiRow += s_rr[g][8 + w]; }
            float e1 = __expf(sc1 - mm);
            {   // reduce2: sum e, max e*neif
                float se = wsum(e1), mn = wmax(e1*nf1);
                if (lane == 0) { s_rr[g][16 + w8] = se; s_rr[g][24 + w8] = mn; }
            }
            __syncthreads();
            float ssum = s_rr[g][16], mpos = s_rr[g][24];
#pragma unroll
            for (int w = 1; w < 8; w++) { ssum += s_rr[g][16 + w]; mpos = fmaxf(mpos, s_rr[g][24 + w]); }
            float inv = 1.f / ssum;
            float maxposRow = mpos * inv;
            if (j1 < NN) s_pos[g][j1] = e1 * inv * nf1;
            {   // active-list compaction
                unsigned b1 = __ballot_sync(0xffffffffu, nf1 > 0.f);
                int base = 0;
                if (lane == 0 && b1) base = atomicAdd(&s_cnt[g], __popc(b1));
                base = __shfl_sync(0xffffffffu, base, 0);
                if (nf1 > 0.f)
                    s_actb[g][base + __popc(b1 & ((1u << lane) - 1u))] = (unsigned char)j1;
            }
            __syncthreads();
            // gate + message loop (8 warps strided over active j)
            const float Ai0 = s_A[g][lane]      + s_bg[STAGE*DH + lane];
            const float Ai1 = s_A[g][32 + lane] + s_bg[STAGE*DH + 32 + lane];
            const float2* wg2 = s_wg2 + STAGE*DR*32;
            float msg0 = 0.f, msg1 = 0.f, v1p = 0.f;
            const int cnt = s_cnt[g];
            for (int a = w8; a < cnt; a += 8) {
                int j = s_actb[g][a];
                float pj = s_pos[g][j];
                float cx = ax - s_abs[2*j], cy = ay - s_abs[2*j+1];
                float2 Bj = __ldcg(&gBp[j*32 + lane]);
                float2 hj = __ldcg(&hp[j*32 + lane]);
                float acc0 = Ai0 + Bj.x;
                float acc1 = Ai1 + Bj.y;
#pragma unroll
                for (int k = 0; k < DR; k++) {
                    float4 c4 = cst[k];
                    float rv = fmaxf(fmaf(cx, c4.x, fmaf(cy, c4.y, c4.z)), 0.f);
                    float2 w2 = wg2[k*32 + lane];
                    acc0 += rv * w2.x;
                    acc1 += rv * w2.y;
                }
                float g0 = 1.f/(1.f+__expf(-acc0));
                float g1 = 1.f/(1.f+__expf(-acc1));
                msg0 += pj*g0*hj.x;
                msg1 += pj*g1*hj.y;
                v1p  += g0 + g1;
            }
            s_msg2[g][w8][lane] = make_float2(msg0, msg1);
            v1p = wsum(v1p);
            if (lane == 0) s_v1[g][w8] = v1p;
            __syncthreads();
            if (ltid < DH) {
                int h = ltid;
                float v = 0.f;
#pragma unroll
                for (int w = 0; w < 8; w++)
                    v += (h < 32) ? s_msg2[g][w][h].x : s_msg2[g][w][h-32].y;
                s_msgf[g][h] = v;
            }
            __syncthreads();
            if (ltid < DH) {
                int h = ltid;
                float cn = s_ctmp[g][h];
                float hn = s_hn[g][h];
                if (cnt) {
                    const float* wn = g_wneiT + STAGE*DH*DH;
#pragma unroll
                    for (int k = 0; k < DH; k++) cn += s_msgf[g][k]*wn[k*DH + h];
                    hn = s_og[g][h]*tanhf(cn);
                }
                s_ctmp[g][h] = cn;
                s_hn[g][h] = hn;
                if (STAGE == 1 && mi) { s_h[g][h] = hn; s_c[g][h] = cn; }
            }
            __syncthreads();
            if (STAGE == 0) {
                if (mi) {   // pre1 + pack h2 (unread when mi==0)
                    if (w8 < 2) {
                        int h = ltid;
                        const float* wp = g_wABT + 2*64*64;     // stage1, part A
                        float acc = 0.f;
#pragma unroll
                        for (int k = 0; k < DH; k++) acc += s_hn[g][k]*wp[k*64 + h];
                        s_A[g][h] = acc;
                    } else if (w8 < 4) {
                        int h = ltid - 64;
                        const float* wp = g_wABT + 3*64*64;     // stage1, part B
                        float acc = 0.f;
#pragma unroll
                        for (int k = 0; k < DH; k++) acc += s_hn[g][k]*wp[k*64 + h];
                        s_gates[g][h] = acc;
                    } else if (w8 == 4) {
                        float pa = s_hn[g][lane]*s_war[128+lane] + s_hn[g][32+lane]*s_war[160+lane];
                        pa = wsum(pa);
                        if (lane == 0) s_a[g] = pa;
                    } else if (w8 == 5) {
                        float pb = s_hn[g][lane]*s_war[192+lane] + s_hn[g][32+lane]*s_war[224+lane];
                        pb = wsum(pb);
                        if (lane == 0) g_b1v[i] = pb;
                    } else if (w8 == 6) {
                        g_h2p[i*32 + lane] = make_float2(s_hn[g][lane], s_hn[g][32 + lane]);
                    }
                    if (ltid == 0) {
                        float gateSum = 0.f;
#pragma unroll
                        for (int w = 0; w < 8; w++) gateSum += s_v1[g][w];
                        atomicAdd(&g_acc[0], gateSum);
                        atomicAdd(&g_acc[1], neiRow);
                        atomicAdd(&g_acc[2], maxposRow);
                        atomicAdd(&g_acc[3], neiRow > 0.f ? 1.f : 0.f);
                    }
                }
                __syncthreads();
                if (mi && w8 == 7)
                    g_B1p[i*32 + lane] = make_float2(s_gates[g][lane], s_gates[g][lane + 32]);
                gbar(sense);
            } else {
                if (ltid < 2) {
                    float o = b_out[ltid];
#pragma unroll
                    for (int k = 0; k < DH; k++) o += s_hn[g][k]*w_out[ltid*DH + k];
                    out[(t*NN + i)*2 + ltid] = mi ? o : 0.f;
                }
            }
        }
        // no barrier between C and next A (A touches only own-row state)
    }

    // final writeback
    const int OFF = TT*NN*2;
    if (ltid < DH) {
        out[OFF + i*DH + ltid]         = s_h[g][ltid];
        out[OFF + NN*DH + i*DH + ltid] = s_c[g][ltid];
    }
    if (blockIdx.x == 0 && tid < 3) out[OFF + 2*NN*DH + tid] = g_v[tid] / (float)TT;
}

extern "C" void kernel_launch(void* const* d_in, const int* in_sizes, int n_in,
                              void* d_out, int out_size) {
    const float* abs_   = (const float*)d_in[0];
    const float* norm   = (const float*)d_in[1];
    const float* w_in   = (const float*)d_in[3];
    const float* b_in   = (const float*)d_in[4];
    const float* w_ih   = (const float*)d_in[5];
    const float* w_hh   = (const float*)d_in[6];
    const float* b_ih   = (const float*)d_in[7];
    const float* b_hh   = (const float*)d_in[8];
    const float* w_rel  = (const float*)d_in[9];
    const float* b_rel  = (const float*)d_in[10];
    const float* w_gate = (const float*)d_in[11];
    const float* b_gate = (const float*)d_in[12];
    const float* w_ar   = (const float*)d_in[13];
    const float* b_ar   = (const float*)d_in[14];
    const float* w_nei  = (const float*)d_in[15];
    const float* w_out  = (const float*)d_in[16];
    const float* b_out  = (const float*)d_in[17];
    const int*   seq    = (const int*)d_in[18];
    const int*   nei    = (const int*)d_in[19];
    float* out = (float*)d_out;

    void* barptr = nullptr;
    cudaGetSymbolAddress(&barptr, g_bar);
    cudaMemsetAsync(barptr, 0, 2*sizeof(unsigned), 0);

    fused_kernel<<<NB, NTH>>>(abs_, norm, w_in, b_in, w_ih, w_hh, b_ih, b_hh,
                              w_rel, b_rel, w_gate, b_gate, w_ar, b_ar,
                              w_nei, w_out, b_out, seq, nei, out);
}

// round 11
// speedup vs baseline: 1.9850x; 1.2550x over previous
#include <cuda_runtime.h>
#include <math.h>

#define NN 192
#define TT 20
#define DH 64
#define DE 32
#define DR 32
#define NB 96
#define NTH 512
#define RPB 2

// ---- device scratch (no allocations allowed) ----
__device__ float4 g_hB0p[NN*32], g_hB1p[NN*32];    // packed {h[l], h[l+32], B[l], B[l+32]}
__device__ float  g_b0v[NN], g_b1v[NN];
__device__ float  g_acc[4], g_v[3];
__device__ unsigned g_bar[2];                      // memset to 0 each launch
// transposed weights (built once)
__device__ float g_wABT[2*2*64*64];                // [p][part][k][h]  (h fastest)
__device__ float g_wneiT[2*64*64];                 // [p][k][h]

struct __align__(16) Smem {
    float4 cst4[2*DR];            // {wrel_x, wrel_y, brel, war_k}
    float2 wl2[96*128];           // LSTM weights [e][pair r]
    float2 wg2[2*DR*32];          // [p][k][lane]{h,h+32}
    float2 msg2[RPB][8][32];
    float  r[RPB][DR*NN];         // [k][j]
    float  war[256];
    float  bcomb[256];
    float  bg[2*DH];
    float  bar2[2];
    float  absv[2*NN];
    float  gates[RPB][256];
    float  xh[RPB][96];
    float  pos[RPB][NN];
    float  hn[RPB][DH];
    float  A[RPB][DH];
    float  a[RPB];
    float  rr[RPB][24];
    float  v1[RPB][8];
    float  h[RPB][DH], c[RPB][DH], og[RPB][DH], ctmp[RPB][DH], msgf[RPB][DH];
    int    cnt[RPB];
    unsigned char seqb[NN];
    unsigned char neib[RPB][NN];
    unsigned char actb[RPB][NN];
};

__device__ __forceinline__ void gbar(unsigned& sense) {
    __syncthreads();
    if (threadIdx.x == 0) {
        unsigned want = sense + 1u;
        __threadfence();
        unsigned a = atomicAdd(&g_bar[0], 1u);
        if (a == NB - 1u) {
            g_bar[0] = 0u;
            asm volatile("st.release.gpu.u32 [%0], %1;" :: "l"(&g_bar[1]), "r"(want) : "memory");
        } else {
            unsigned v;
            for (;;) {
                asm volatile("ld.acquire.gpu.u32 %0, [%1];" : "=r"(v) : "l"(&g_bar[1]) : "memory");
                if (v >= want) break;
                __nanosleep(32);
            }
        }
    }
    __syncthreads();
    sense += 1u;
}

__device__ __forceinline__ float wsum(float v) {
#pragma unroll
    for (int o = 16; o; o >>= 1) v += __shfl_xor_sync(0xffffffffu, v, o);
    return v;
}
__device__ __forceinline__ float wmax(float v) {
#pragma unroll
    for (int o = 16; o; o >>= 1) v = fmaxf(v, __shfl_xor_sync(0xffffffffu, v, o));
    return v;
}

__global__ void __launch_bounds__(NTH, 1)
fused_kernel(const float* __restrict__ abs_, const float* __restrict__ norm,
             const float* __restrict__ w_in, const float* __restrict__ b_in,
             const float* __restrict__ w_ih, const float* __restrict__ w_hh,
             const float* __restrict__ b_ih, const float* __restrict__ b_hh,
             const float* __restrict__ w_rel, const float* __restrict__ b_rel,
             const float* __restrict__ w_gate, const float* __restrict__ b_gate,
             const float* __restrict__ w_ar, const float* __restrict__ b_ar,
             const float* __restrict__ w_nei, const float* __restrict__ w_out,
             const float* __restrict__ b_out,
             const int* __restrict__ seq, const int* __restrict__ nei,
             float* __restrict__ out)
{
    extern __shared__ char smem_raw[];
    Smem& S = *reinterpret_cast<Smem*>(smem_raw);

    const int tid  = threadIdx.x;
    const int g    = tid >> 8;            // row group 0..1
    const int ltid = tid & 255;           // 0..255 within group
    const int lane = tid & 31;
    const int w8   = (tid >> 5) & 7;      // warp within group 0..7
    const int i    = blockIdx.x * RPB + g;
    const int gtid = blockIdx.x * NTH + tid;
    unsigned sense = 0;

    // ---- one-time smem constant loads ----
    for (int idx = tid; idx < 96*128; idx += NTH) {
        int e = idx >> 7, p = idx & 127;
        int r0 = 2*p, r1 = 2*p + 1;
        float v0, v1;
        if (e < DE) { v0 = w_ih[r0*DE + e];        v1 = w_ih[r1*DE + e]; }
        else        { v0 = w_hh[r0*DH + (e - DE)]; v1 = w_hh[r1*DH + (e - DE)]; }
        S.wl2[idx] = make_float2(v0, v1);
    }
    for (int idx = tid; idx < 2*DR*32; idx += NTH) {
        int p = idx >> 10, rem = idx & 1023, k = rem >> 5, l = rem & 31;
        S.wg2[idx] = make_float2(w_gate[p*DH*160 + l*160 + k],
                                 w_gate[p*DH*160 + (l+32)*160 + k]);
    }
    for (int idx = tid; idx < 2*DR; idx += NTH) {
        int p = idx >> 5, k = idx & 31;
        S.cst4[idx] = make_float4(w_rel[p*DR*2 + k*2 + 0], w_rel[p*DR*2 + k*2 + 1],
                                  b_rel[p*DR + k],          w_ar[p*160 + k]);
    }
    for (int idx = tid; idx < 256; idx += NTH) {
        int p = idx >> 7, part = (idx >> 6) & 1, k = idx & 63;
        S.war[idx] = w_ar[p*160 + 32 + part*64 + k];
    }
    if (tid < 256) S.bcomb[tid] = b_ih[tid] + b_hh[tid];
    if (tid < 2*DH) S.bg[tid] = b_gate[tid];
    if (tid < 2) S.bar2[tid] = b_ar[tid];
    if (ltid < DH) { S.h[g][ltid] = 0.f; S.c[g][ltid] = 0.f; }

    // ---- one-time global transposes + zero init ----
    for (int idx = gtid; idx < 2*2*64*64; idx += NB*NTH) {
        int h = idx & 63, k = (idx >> 6) & 63, part = (idx >> 12) & 1, p = idx >> 13;
        g_wABT[idx] = w_gate[p*DH*160 + h*160 + 32 + part*64 + k];
    }
    for (int idx = gtid; idx < 2*64*64; idx += NB*NTH) {
        int h = idx & 63, k = (idx >> 6) & 63, p = idx >> 12;
        g_wneiT[idx] = w_nei[p*DH*DH + h*DH + k];
    }
    if (gtid < NN*2) out[(TT-1)*NN*2 + gtid] = 0.f;
    if (blockIdx.x == 0 && tid < 4) g_acc[tid] = 0.f;
    if (blockIdx.x == 0 && tid < 3) g_v[tid] = 0.f;
    gbar(sense);

    for (int t = 0; t < TT-1; t++) {
        //================ Phase A: prefetch + LSTM + pre0 ================
        if (tid < 2*NN) S.absv[tid] = abs_[t*NN*2 + tid];
        if (tid < NN)   S.seqb[tid] = (unsigned char)(seq[t*NN + tid] > 0);
        if (ltid < NN)  S.neib[g][ltid] =
            (unsigned char)(nei[(size_t)t*NN*NN + (size_t)i*NN + ltid] > 0);
        if (ltid < DE) {
            float n0 = norm[(t*NN + i)*2 + 0];
            float n1 = norm[(t*NN + i)*2 + 1];
            S.xh[g][ltid] = fmaxf(n0*w_in[ltid*2 + 0] + n1*w_in[ltid*2 + 1] + b_in[ltid], 0.f);
        }
        if (ltid >= 64 && ltid < 128) S.xh[g][32 + (ltid - 64)] = S.h[g][ltid - 64];
        __syncthreads();
        const int mi = S.seqb[i];
        if (ltid < 128) {   // LSTM gates: 2 per thread via float2
            const float2* bc2 = (const float2*)S.bcomb;
            float2 acc = bc2[ltid];
#pragma unroll
            for (int e = 0; e < 96; e++) {
                float xv = S.xh[g][e];
                float2 w2 = S.wl2[e*128 + ltid];
                acc.x += xv * w2.x;
                acc.y += xv * w2.y;
            }
            ((float2*)S.gates[g])[ltid] = acc;
        }
        __syncthreads();
        if (ltid < DH) {
            int h = ltid;
            float ig = 1.f/(1.f+__expf(-S.gates[g][h]));
            float fg = 1.f/(1.f+__expf(-S.gates[g][64 + h]));
            float gg = tanhf(S.gates[g][128 + h]);
            float og = 1.f/(1.f+__expf(-S.gates[g][192 + h]));
            float c1 = fg*S.c[g][h] + ig*gg;
            float h1 = og*tanhf(c1);
            S.ctmp[g][h] = c1;
            S.og[g][h] = og;
            S.hn[g][h] = h1;
        }
        __syncthreads();
        if (mi) {   // pre0 (results unread when mi==0)
            if (w8 == 0) {          // part A -> s_A (float2 over h)
                const float2* wp = (const float2*)(g_wABT + 0*4096);
                float ax2 = 0.f, ay2 = 0.f;
#pragma unroll
                for (int k = 0; k < DH; k++) {
                    float hk = S.hn[g][k];
                    float2 w2 = wp[k*32 + lane];
                    ax2 += hk*w2.x; ay2 += hk*w2.y;
                }
                ((float2*)S.A[g])[lane] = make_float2(ax2, ay2);
            } else if (w8 == 1) {   // part B -> gates scratch
                const float2* wp = (const float2*)(g_wABT + 1*4096);
                float bx = 0.f, by = 0.f;
#pragma unroll
                for (int k = 0; k < DH; k++) {
                    float hk = S.hn[g][k];
                    float2 w2 = wp[k*32 + lane];
                    bx += hk*w2.x; by += hk*w2.y;
                }
                ((float2*)S.gates[g])[lane] = make_float2(bx, by);
            } else if (w8 == 2) {
                float pa = S.hn[g][lane]*S.war[lane] + S.hn[g][32+lane]*S.war[32+lane];
                pa = wsum(pa);
                if (lane == 0) S.a[g] = pa;
            } else if (w8 == 3) {
                float pb = S.hn[g][lane]*S.war[64+lane] + S.hn[g][32+lane]*S.war[96+lane];
                pb = wsum(pb);
                if (lane == 0) g_b0v[i] = pb;
            }
        }
        __syncthreads();
        if (mi && w8 == 4)
            g_hB0p[i*32 + lane] = make_float4(S.hn[g][lane], S.hn[g][32 + lane],
                                              S.gates[g][lane], S.gates[g][lane + 32]);
        gbar(sense);

        //================ Phases B (stage0) and C (stage1) ================
#pragma unroll 1
        for (int STAGE = 0; STAGE < 2; STAGE++) {
            if (STAGE == 1 && blockIdx.x == 0 && tid == 0) {
                const float eps = 1e-6f;
                g_v[0] += g_acc[0] / (g_acc[1]*(float)DH + eps);
                g_v[1] += g_acc[2] / (g_acc[3] + eps);
                g_v[2] += g_acc[1] / (float)NN;
                g_acc[0] = g_acc[1] = g_acc[2] = g_acc[3] = 0.f;
            }
            const float4* hBp = STAGE ? g_hB1p : g_hB0p;
            const float*  gbv = STAGE ? g_b1v : g_b0v;
            const float   barv = S.bar2[STAGE];
            const float   aI   = S.a[g];
            const float   ax = S.absv[2*i], ay = S.absv[2*i+1];
            const float4* cst = S.cst4 + STAGE*DR;

            if (ltid == 0) S.cnt[g] = 0;
            // scores (one j per thread) + cache r[k][j] in smem
            float nf1 = 0.f, sc1 = -1e30f;
            const int j1 = ltid;
            if (mi && j1 < NN) {
                nf1 = (S.neib[g][j1] && S.seqb[j1]) ? 1.f : 0.f;
                float cx = ax - S.absv[2*j1], cy = ay - S.absv[2*j1+1];
                float sc = 0.f;
#pragma unroll
                for (int k = 0; k < DR; k++) {
                    float4 c4 = cst[k];
                    float rv = fmaxf(fmaf(cx, c4.x, fmaf(cy, c4.y, c4.z)), 0.f);
                    S.r[g][k*NN + j1] = rv;
                    sc += rv * c4.w;
                }
                sc += aI + __ldcg(&gbv[j1]) + barv;
                sc1 = (nf1 > 0.f) ? sc : -1e9f;
            }
            // single merged reduction: sum(e), max(e*nf), sum(nf)
            float e1 = __expf(sc1);     // masked/-inf -> 0
            {
                float se = wsum(e1), mn = wmax(e1*nf1), sn = wsum(nf1);
                if (lane == 0) { S.rr[g][w8] = se; S.rr[g][8+w8] = mn; S.rr[g][16+w8] = sn; }
            }
            __syncthreads();
            float ssum = 0.f, mpos = 0.f, neiRow = 0.f;
#pragma unroll
            for (int w = 0; w < 8; w++) {
                ssum += S.rr[g][w];
                mpos = fmaxf(mpos, S.rr[g][8+w]);
                neiRow += S.rr[g][16+w];
            }
            float inv = (ssum > 0.f) ? 1.f/ssum : 0.f;
            float maxposRow = mpos * inv;
            if (j1 < NN) S.pos[g][j1] = e1 * inv * nf1;
            {   // active-list compaction
                unsigned b1 = __ballot_sync(0xffffffffu, nf1 > 0.f);
                int base = 0;
                if (lane == 0 && b1) base = atomicAdd(&S.cnt[g], __popc(b1));
                base = __shfl_sync(0xffffffffu, base, 0);
                if (nf1 > 0.f)
                    S.actb[g][base + __popc(b1 & ((1u << lane) - 1u))] = (unsigned char)j1;
            }
            __syncthreads();
            // gate + message loop: 2 neighbors per iteration, 8 warps strided
            const float Ai0 = S.A[g][lane]      + S.bg[STAGE*DH + lane];
            const float Ai1 = S.A[g][32 + lane] + S.bg[STAGE*DH + 32 + lane];
            const float2* wg2 = S.wg2 + STAGE*DR*32;
            const float*  rS  = S.r[g];
            float msg0 = 0.f, msg1 = 0.f, v1p = 0.f;
            const int cnt = S.cnt[g];
            for (int a = 2*w8; a < cnt; a += 16) {
                int ja = S.actb[g][a];
                bool two = (a + 1) < cnt;
                int jb = two ? S.actb[g][a+1] : ja;
                float pa = S.pos[g][ja];
                float pb = two ? S.pos[g][jb] : 0.f;
                float4 HA = __ldcg(&hBp[ja*32 + lane]);
                float4 HB = __ldcg(&hBp[jb*32 + lane]);
                float a0 = Ai0 + HA.z, a1 = Ai1 + HA.w;
                float b0 = Ai0 + HB.z, b1 = Ai1 + HB.w;
#pragma unroll
                for (int k = 0; k < DR; k++) {
                    float rva = rS[k*NN + ja];
                    float rvb = rS[k*NN + jb];
                    float2 w2 = wg2[k*32 + lane];
                    a0 += rva * w2.x; a1 += rva * w2.y;
                    b0 += rvb * w2.x; b1 += rvb * w2.y;
                }
                float ga0 = 1.f/(1.f+__expf(-a0));
                float ga1 = 1.f/(1.f+__expf(-a1));
                float gb0 = 1.f/(1.f+__expf(-b0));
                float gb1 = 1.f/(1.f+__expf(-b1));
                msg0 += pa*ga0*HA.x + pb*gb0*HB.x;
                msg1 += pa*ga1*HA.y + pb*gb1*HB.y;
                v1p  += ga0 + ga1 + gb0 + gb1;
            }
            S.msg2[g][w8][lane] = make_float2(msg0, msg1);
            v1p = wsum(v1p);
            if (lane == 0) S.v1[g][w8] = v1p;
            __syncthreads();
            if (ltid < DH) {
                int h = ltid;
                float v = 0.f;
#pragma unroll
                for (int w = 0; w < 8; w++)
                    v += (h < 32) ? S.msg2[g][w][h].x : S.msg2[g][w][h-32].y;
                S.msgf[g][h] = v;
            }
            __syncthreads();
            if (ltid < DH) {
                int h = ltid;
                float cn = S.ctmp[g][h];
                float hn = S.hn[g][h];
                if (cnt) {
                    const float* wn = g_wneiT + STAGE*DH*DH;
#pragma unroll
                    for (int k = 0; k < DH; k++) cn += S.msgf[g][k]*wn[k*DH + h];
                    hn = S.og[g][h]*tanhf(cn);
                }
                S.ctmp[g][h] = cn;
                S.hn[g][h] = hn;
                if (STAGE == 1 && mi) { S.h[g][h] = hn; S.c[g][h] = cn; }
            }
            __syncthreads();
            if (STAGE == 0) {
                if (mi) {   // pre1 (unread when mi==0)
                    if (w8 == 0) {
                        const float2* wp = (const float2*)(g_wABT + 2*4096);
                        float ax2 = 0.f, ay2 = 0.f;
#pragma unroll
                        for (int k = 0; k < DH; k++) {
                            float hk = S.hn[g][k];
                            float2 w2 = wp[k*32 + lane];
                            ax2 += hk*w2.x; ay2 += hk*w2.y;
                        }
                        ((float2*)S.A[g])[lane] = make_float2(ax2, ay2);
                    } else if (w8 == 1) {
                        const float2* wp = (const float2*)(g_wABT + 3*4096);
                        float bx = 0.f, by = 0.f;
#pragma unroll
                        for (int k = 0; k < DH; k++) {
                            float hk = S.hn[g][k];
                            float2 w2 = wp[k*32 + lane];
                            bx += hk*w2.x; by += hk*w2.y;
                        }
                        ((float2*)S.gates[g])[lane] = make_float2(bx, by);
                    } else if (w8 == 2) {
                        float pa = S.hn[g][lane]*S.war[128+lane] + S.hn[g][32+lane]*S.war[160+lane];
                        pa = wsum(pa);
                        if (lane == 0) S.a[g] = pa;
                    } else if (w8 == 3) {
                        float pb = S.hn[g][lane]*S.war[192+lane] + S.hn[g][32+lane]*S.war[224+lane];
                        pb = wsum(pb);
                        if (lane == 0) g_b1v[i] = pb;
                    }
                    if (ltid == 0) {
                        float gateSum = 0.f;
#pragma unroll
                        for (int w = 0; w < 8; w++) gateSum += S.v1[g][w];
                        atomicAdd(&g_acc[0], gateSum);
                        atomicAdd(&g_acc[1], neiRow);
                        atomicAdd(&g_acc[2], maxposRow);
                        atomicAdd(&g_acc[3], neiRow > 0.f ? 1.f : 0.f);
                    }
                }
                __syncthreads();
                if (mi && w8 == 4)
                    g_hB1p[i*32 + lane] = make_float4(S.hn[g][lane], S.hn[g][32 + lane],
                                                      S.gates[g][lane], S.gates[g][lane + 32]);
                gbar(sense);
            } else {
                if (ltid < 2) {
                    float o = b_out[ltid];
#pragma unroll
                    for (int k = 0; k < DH; k++) o += S.hn[g][k]*w_out[ltid*DH + k];
                    out[(t*NN + i)*2 + ltid] = mi ? o : 0.f;
                }
            }
        }
        // no barrier between C and next A (A touches only own-row state)
    }

    // final writeback
    const int OFF = TT*NN*2;
    if (ltid < DH) {
        out[OFF + i*DH + ltid]         = S.h[g][ltid];
        out[OFF + NN*DH + i*DH + ltid] = S.c[g][ltid];
    }
    if (blockIdx.x == 0 && tid < 3) out[OFF + 2*NN*DH + tid] = g_v[tid] / (float)TT;
}

extern "C" void kernel_launch(void* const* d_in, const int* in_sizes, int n_in,
                              void* d_out, int out_size) {
    const float* abs_   = (const float*)d_in[0];
    const float* norm   = (const float*)d_in[1];
    const float* w_in   = (const float*)d_in[3];
    const float* b_in   = (const float*)d_in[4];
    const float* w_ih   = (const float*)d_in[5];
    const float* w_hh   = (const float*)d_in[6];
    const float* b_ih   = (const float*)d_in[7];
    const float* b_hh   = (const float*)d_in[8];
    const float* w_rel  = (const float*)d_in[9];
    const float* b_rel  = (const float*)d_in[10];
    const float* w_gate = (const float*)d_in[11];
    const float* b_gate = (const float*)d_in[12];
    const float* w_ar   = (const float*)d_in[13];
    const float* b_ar   = (const float*)d_in[14];
    const float* w_nei  = (const float*)d_in[15];
    const float* w_out  = (const float*)d_in[16];
    const float* b_out  = (const float*)d_in[17];
    const int*   seq    = (const int*)d_in[18];
    const int*   nei    = (const int*)d_in[19];
    float* out = (float*)d_out;

    cudaFuncSetAttribute(fused_kernel, cudaFuncAttributeMaxDynamicSharedMemorySize,
                         (int)sizeof(Smem));

    void* barptr = nullptr;
    cudaGetSymbolAddress(&barptr, g_bar);
    cudaMemsetAsync(barptr, 0, 2*sizeof(unsigned), 0);

    fused_kernel<<<NB, NTH, sizeof(Smem)>>>(abs_, norm, w_in, b_in, w_ih, w_hh, b_ih, b_hh,
                                            w_rel, b_rel, w_gate, b_gate, w_ar, b_ar,
                                            w_nei, w_out, b_out, seq, nei, out);
}

// round 12
// speedup vs baseline: 2.1643x; 1.0903x over previous
#include <cuda_runtime.h>
#include <math.h>

#define NN 192
#define TT 20
#define DH 64
#define DE 32
#define DR 32
#define NB 96
#define NTH 512
#define RPB 2

// ---- device scratch (no allocations allowed) ----
__device__ float4 g_hB0p[NN*32], g_hB1p[NN*32];    // packed {h[l], h[l+32], B[l], B[l+32]}
__device__ float  g_b0v[NN], g_b1v[NN];
__device__ float  g_acc[4], g_v[3];
__device__ unsigned g_bar[1];                      // memset to 0 each launch
__device__ float g_wABT[2*2*64*64];                // [p][part][k][h] (h fastest)

struct __align__(16) Smem {
    float4 cst4[2*DR];            // {wrel_x, wrel_y, brel, war_k}
    float2 wl2[96*128];           // LSTM weights [e][pair r]
    float2 wg2[2*DR*32];          // [p][k][lane]{h,h+32}
    float2 msg2[RPB][8][32];
    float2 pre2[RPB][4][32];      // pre-GEMV partials
    float  wnei[2*64*64];         // [p][k][h]
    float  r[RPB][DR*NN];         // [k][j]
    float  war[256];
    float  bcomb[256];
    float  bg[2*DH];
    float  bar2[2];
    float  wout[2*DH];
    float  bout[2];
    float  absv[RPB][2*NN];       // per-group copy (group decoupling)
    float  gates[RPB][256];
    float  xh[RPB][96];
    float  pos[RPB][NN];
    float  hn[RPB][DH];
    float  A[RPB][DH];
    float  cnp[RPB][DH];
    float  a[RPB];
    float  rr[RPB][24];
    float  v1[RPB][8];
    float  h[RPB][DH], c[RPB][DH], og[RPB][DH], ctmp[RPB][DH], msgf[RPB][DH];
    int    cnt[RPB];
    unsigned char seqb[RPB][NN];  // per-group copy
    unsigned char neib[RPB][NN];
    unsigned char actb[RPB][NN];
};

// group-local barrier: 256 threads of row-group g (named barrier g+1)
__device__ __forceinline__ void rbar(int g) {
    asm volatile("bar.sync %0, %1;" :: "r"(g + 1), "r"(256) : "memory");
}

// grid barrier: monotonic counter, red-arrive + acquire poll
__device__ __forceinline__ void gbar(unsigned& target) {
    __syncthreads();
    if (threadIdx.x == 0) {
        target += NB;
        __threadfence();
        asm volatile("red.release.gpu.add.u32 [%0], 1;" :: "l"(g_bar) : "memory");
        unsigned v;
        do {
            asm volatile("ld.acquire.gpu.u32 %0, [%1];" : "=r"(v) : "l"(g_bar) : "memory");
        } while ((int)(v - target) < 0);
    }
    __syncthreads();
}

__device__ __forceinline__ float wsum(float v) {
#pragma unroll
    for (int o = 16; o; o >>= 1) v += __shfl_xor_sync(0xffffffffu, v, o);
    return v;
}
__device__ __forceinline__ float wmax(float v) {
#pragma unroll
    for (int o = 16; o; o >>= 1) v = fmaxf(v, __shfl_xor_sync(0xffffffffu, v, o));
    return v;
}

__global__ void __launch_bounds__(NTH, 1)
fused_kernel(const float* __restrict__ abs_, const float* __restrict__ norm,
             const float* __restrict__ w_in, const float* __restrict__ b_in,
             const float* __restrict__ w_ih, const float* __restrict__ w_hh,
             const float* __restrict__ b_ih, const float* __restrict__ b_hh,
             const float* __restrict__ w_rel, const float* __restrict__ b_rel,
             const float* __restrict__ w_gate, const float* __restrict__ b_gate,
             const float* __restrict__ w_ar, const float* __restrict__ b_ar,
             const float* __restrict__ w_nei, const float* __restrict__ w_out,
             const float* __restrict__ b_out,
             const int* __restrict__ seq, const int* __restrict__ nei,
             float* __restrict__ out)
{
    extern __shared__ char smem_raw[];
    Smem& S = *reinterpret_cast<Smem*>(smem_raw);

    const int tid  = threadIdx.x;
    const int g    = tid >> 8;            // row group 0..1
    const int ltid = tid & 255;           // 0..255 within group
    const int lane = tid & 31;
    const int w8   = (tid >> 5) & 7;      // warp within group 0..7
    const int i    = blockIdx.x * RPB + g;
    const int gtid = blockIdx.x * NTH + tid;
    unsigned target = 0;

    // ---- one-time smem constant loads ----
    for (int idx = tid; idx < 96*128; idx += NTH) {
        int e = idx >> 7, p = idx & 127;
        int r0 = 2*p, r1 = 2*p + 1;
        float v0, v1;
        if (e < DE) { v0 = w_ih[r0*DE + e];        v1 = w_ih[r1*DE + e]; }
        else        { v0 = w_hh[r0*DH + (e - DE)]; v1 = w_hh[r1*DH + (e - DE)]; }
        S.wl2[idx] = make_float2(v0, v1);
    }
    for (int idx = tid; idx < 2*DR*32; idx += NTH) {
        int p = idx >> 10, rem = idx & 1023, k = rem >> 5, l = rem & 31;
        S.wg2[idx] = make_float2(w_gate[p*DH*160 + l*160 + k],
                                 w_gate[p*DH*160 + (l+32)*160 + k]);
    }
    for (int idx = tid; idx < 2*64*64; idx += NTH) {
        int h = idx & 63, k = (idx >> 6) & 63, p = idx >> 12;
        S.wnei[idx] = w_nei[p*DH*DH + h*DH + k];
    }
    for (int idx = tid; idx < 2*DR; idx += NTH) {
        int p = idx >> 5, k = idx & 31;
        S.cst4[idx] = make_float4(w_rel[p*DR*2 + k*2 + 0], w_rel[p*DR*2 + k*2 + 1],
                                  b_rel[p*DR + k],          w_ar[p*160 + k]);
    }
    for (int idx = tid; idx < 256; idx += NTH) {
        int p = idx >> 7, part = (idx >> 6) & 1, k = idx & 63;
        S.war[idx] = w_ar[p*160 + 32 + part*64 + k];
    }
    if (tid < 256) S.bcomb[tid] = b_ih[tid] + b_hh[tid];
    if (tid < 2*DH) S.bg[tid] = b_gate[tid];
    if (tid < 128) S.wout[tid] = w_out[tid];
    if (tid < 2) { S.bar2[tid] = b_ar[tid]; S.bout[tid] = b_out[tid]; }
    if (ltid < DH) { S.h[g][ltid] = 0.f; S.c[g][ltid] = 0.f; }

    // ---- one-time global transposes + zero init ----
    for (int idx = gtid; idx < 2*2*64*64; idx += NB*NTH) {
        int h = idx & 63, k = (idx >> 6) & 63, part = (idx >> 12) & 1, p = idx >> 13;
        g_wABT[idx] = w_gate[p*DH*160 + h*160 + 32 + part*64 + k];
    }
    if (gtid < NN*2) out[(TT-1)*NN*2 + gtid] = 0.f;
    if (blockIdx.x == 0 && tid < 4) g_acc[tid] = 0.f;
    if (blockIdx.x == 0 && tid < 3) g_v[tid] = 0.f;
    gbar(target);

    for (int t = 0; t < TT-1; t++) {
        //================ Phase A: prefetch + LSTM + pre0 ================
        {
            S.absv[g][ltid] = abs_[t*NN*2 + ltid];
            if (ltid < 2*NN - 256) S.absv[g][256 + ltid] = abs_[t*NN*2 + 256 + ltid];
            if (ltid < NN) {
                S.seqb[g][ltid] = (unsigned char)(seq[t*NN + ltid] > 0);
                S.neib[g][ltid] =
                    (unsigned char)(nei[(size_t)t*NN*NN + (size_t)i*NN + ltid] > 0);
            }
            if (ltid < DE) {
                float n0 = norm[(t*NN + i)*2 + 0];
                float n1 = norm[(t*NN + i)*2 + 1];
                S.xh[g][ltid] = fmaxf(n0*w_in[ltid*2+0] + n1*w_in[ltid*2+1] + b_in[ltid], 0.f);
            }
            if (ltid >= 64 && ltid < 128) S.xh[g][32 + (ltid - 64)] = S.h[g][ltid - 64];
        }
        rbar(g);
        const int mi = S.seqb[g][i];
        if (ltid < 128) {   // LSTM gates: 2 per thread via float2
            const float2* bc2 = (const float2*)S.bcomb;
            float2 acc = bc2[ltid];
#pragma unroll
            for (int e = 0; e < 96; e++) {
                float xv = S.xh[g][e];
                float2 w2 = S.wl2[e*128 + ltid];
                acc.x += xv * w2.x;
                acc.y += xv * w2.y;
            }
            ((float2*)S.gates[g])[ltid] = acc;
        }
        rbar(g);
        if (ltid < DH) {
            int h = ltid;
            float ig = 1.f/(1.f+__expf(-S.gates[g][h]));
            float fg = 1.f/(1.f+__expf(-S.gates[g][64 + h]));
            float gg = tanhf(S.gates[g][128 + h]);
            float og = 1.f/(1.f+__expf(-S.gates[g][192 + h]));
            float c1 = fg*S.c[g][h] + ig*gg;
            float h1 = og*tanhf(c1);
            S.ctmp[g][h] = c1;
            S.og[g][h] = og;
            S.hn[g][h] = h1;
        }
        rbar(g);
        if (mi) {   // pre0 partials: 4 warps, k split in halves
            if (w8 < 4) {
                int part = w8 >> 1, khalf = w8 & 1;
                const float2* wp = (const float2*)(g_wABT + part*4096);
                float sx = 0.f, sy = 0.f;
#pragma unroll
                for (int kk = 0; kk < 32; kk++) {
                    int k = khalf*32 + kk;
                    float hk = S.hn[g][k];
                    float2 w2 = wp[k*32 + lane];
                    sx += hk*w2.x; sy += hk*w2.y;
                }
                S.pre2[g][w8][lane] = make_float2(sx, sy);
            } else if (w8 == 4) {
                float pa = S.hn[g][lane]*S.war[lane] + S.hn[g][32+lane]*S.war[32+lane];
                pa = wsum(pa);
                if (lane == 0) S.a[g] = pa;
            } else if (w8 == 5) {
                float pb = S.hn[g][lane]*S.war[64+lane] + S.hn[g][32+lane]*S.war[96+lane];
                pb = wsum(pb);
                if (lane == 0) g_b0v[i] = pb;
            }
        }
        rbar(g);
        if (mi) {
            if (w8 == 0) {
                float2 p0 = S.pre2[g][0][lane], p1 = S.pre2[g][1][lane];
                ((float2*)S.A[g])[lane] = make_float2(p0.x + p1.x, p0.y + p1.y);
            } else if (w8 == 1) {
                float2 q0 = S.pre2[g][2][lane], q1 = S.pre2[g][3][lane];
                ((float2*)S.gates[g])[lane] = make_float2(q0.x + q1.x, q0.y + q1.y);
                __syncwarp();
                g_hB0p[i*32 + lane] = make_float4(S.hn[g][lane], S.hn[g][32 + lane],
                                                  S.gates[g][lane], S.gates[g][lane + 32]);
            }
        }
        gbar(target);

        //================ Phases B (stage0) and C (stage1) ================
#pragma unroll 1
        for (int STAGE = 0; STAGE < 2; STAGE++) {
            if (STAGE == 1 && blockIdx.x == 0 && tid == 0) {
                const float eps = 1e-6f;
                g_v[0] += g_acc[0] / (g_acc[1]*(float)DH + eps);
                g_v[1] += g_acc[2] / (g_acc[3] + eps);
                g_v[2] += g_acc[1] / (float)NN;
                g_acc[0] = g_acc[1] = g_acc[2] = g_acc[3] = 0.f;
            }
            const float4* hBp = STAGE ? g_hB1p : g_hB0p;
            const float*  gbv = STAGE ? g_b1v : g_b0v;
            const float   barv = S.bar2[STAGE];
            const float   aI   = S.a[g];
            const float   ax = S.absv[g][2*i], ay = S.absv[g][2*i+1];
            const float4* cst = S.cst4 + STAGE*DR;

            if (ltid == 0) S.cnt[g] = 0;
            // scores (one j per thread) + cache r[k][j]
            float nf1 = 0.f, sc1 = -1e30f;
            const int j1 = ltid;
            if (mi && j1 < NN) {
                nf1 = (S.neib[g][j1] && S.seqb[g][j1]) ? 1.f : 0.f;
                float bj = __ldcg(&gbv[j1]);
                float cx = ax - S.absv[g][2*j1], cy = ay - S.absv[g][2*j1+1];
                float sc = 0.f;
#pragma unroll
                for (int k = 0; k < DR; k++) {
                    float4 c4 = cst[k];
                    float rv = fmaxf(fmaf(cx, c4.x, fmaf(cy, c4.y, c4.z)), 0.f);
                    S.r[g][k*NN + j1] = rv;
                    sc += rv * c4.w;
                }
                sc += aI + bj + barv;
                sc1 = (nf1 > 0.f) ? sc : -1e9f;
            }
            float e1 = __expf(sc1);     // masked -> 0
            {   // merged reduction: sum(e), max(e*nf), sum(nf)
                float se = wsum(e1), mn = wmax(e1*nf1), sn = wsum(nf1);
                if (lane == 0) { S.rr[g][w8] = se; S.rr[g][8+w8] = mn; S.rr[g][16+w8] = sn; }
            }
            rbar(g);
            float ssum = 0.f, mpos = 0.f, neiRow = 0.f;
#pragma unroll
            for (int w = 0; w < 8; w++) {
                ssum += S.rr[g][w];
                mpos = fmaxf(mpos, S.rr[g][8+w]);
                neiRow += S.rr[g][16+w];
            }
            float inv = (ssum > 0.f) ? 1.f/ssum : 0.f;
            float maxposRow = mpos * inv;
            if (j1 < NN) S.pos[g][j1] = e1 * inv * nf1;
            {   // active-list compaction
                unsigned b1 = __ballot_sync(0xffffffffu, nf1 > 0.f);
                int base = 0;
                if (lane == 0 && b1) base = atomicAdd(&S.cnt[g], __popc(b1));
                base = __shfl_sync(0xffffffffu, base, 0);
                if (nf1 > 0.f)
                    S.actb[g][base + __popc(b1 & ((1u << lane) - 1u))] = (unsigned char)j1;
            }
            rbar(g);
            // gate + message loop: 2 neighbors per iteration, 8 warps strided
            const float Ai0 = S.A[g][lane]      + S.bg[STAGE*DH + lane];
            const float Ai1 = S.A[g][32 + lane] + S.bg[STAGE*DH + 32 + lane];
            const float2* wg2 = S.wg2 + STAGE*DR*32;
            const float*  rS  = S.r[g];
            float msg0 = 0.f, msg1 = 0.f, v1p = 0.f;
            const int cnt = S.cnt[g];
            for (int a = 2*w8; a < cnt; a += 16) {
                int ja = S.actb[g][a];
                bool two = (a + 1) < cnt;
                int jb = two ? S.actb[g][a+1] : ja;
                float pa = S.pos[g][ja];
                float pb = two ? S.pos[g][jb] : 0.f;
                float4 HA = __ldcg(&hBp[ja*32 + lane]);
                float4 HB = __ldcg(&hBp[jb*32 + lane]);
                float a0 = Ai0 + HA.z, a1 = Ai1 + HA.w;
                float b0 = Ai0 + HB.z, b1 = Ai1 + HB.w;
#pragma unroll
                for (int k = 0; k < DR; k++) {
                    float rva = rS[k*NN + ja];
                    float rvb = rS[k*NN + jb];
                    float2 w2 = wg2[k*32 + lane];
                    a0 += rva * w2.x; a1 += rva * w2.y;
                    b0 += rvb * w2.x; b1 += rvb * w2.y;
                }
                float ga0 = 1.f/(1.f+__expf(-a0));
                float ga1 = 1.f/(1.f+__expf(-a1));
                float gb0 = 1.f/(1.f+__expf(-b0));
                float gb1 = 1.f/(1.f+__expf(-b1));
                msg0 += pa*ga0*HA.x + pb*gb0*HB.x;
                msg1 += pa*ga1*HA.y + pb*gb1*HB.y;
                v1p  += ga0 + ga1;
                if (two) v1p += gb0 + gb1;   // FIX: don't count duplicated tail neighbor
            }
            S.msg2[g][w8][lane] = make_float2(msg0, msg1);
            if (STAGE == 0) {
                v1p = wsum(v1p);
                if (lane == 0) S.v1[g][w8] = v1p;
            }
            rbar(g);
            if (ltid < DH) {
                int h = ltid;
                float v = 0.f;
#pragma unroll
                for (int w = 0; w < 8; w++)
                    v += (h < 32) ? S.msg2[g][w][h].x : S.msg2[g][w][h-32].y;
                S.msgf[g][h] = v;
            }
            rbar(g);
            // c update GEMV split across 128 threads (k in halves)
            float accPart = 0.f;
            if (ltid < 128) {
                int part = ltid >> 6, h = ltid & 63;
                const float* wn = S.wnei + STAGE*4096;
#pragma unroll
                for (int kk = 0; kk < 32; kk++) {
                    int k = part*32 + kk;
                    accPart += S.msgf[g][k] * wn[k*64 + h];
                }
                if (part) S.cnp[g][h] = accPart;
            }
            rbar(g);
            if (ltid < DH) {
                int h = ltid;
                float cn = S.ctmp[g][h] + accPart + S.cnp[g][h];
                float hn = S.og[g][h]*tanhf(cn);
                S.ctmp[g][h] = cn;
                S.hn[g][h] = hn;
                if (STAGE == 1 && mi) { S.h[g][h] = hn; S.c[g][h] = cn; }
            }
            rbar(g);
            if (STAGE == 0) {
                if (mi) {   // pre1 partials + stats
                    if (w8 < 4) {
                        int part = w8 >> 1, khalf = w8 & 1;
                        const float2* wp = (const float2*)(g_wABT + (2 + part)*4096);
                        float sx = 0.f, sy = 0.f;
#pragma unroll
                        for (int kk = 0; kk < 32; kk++) {
                            int k = khalf*32 + kk;
                            float hk = S.hn[g][k];
                            float2 w2 = wp[k*32 + lane];
                            sx += hk*w2.x; sy += hk*w2.y;
                        }
                        S.pre2[g][w8][lane] = make_float2(sx, sy);
                    } else if (w8 == 4) {
                        float pa = S.hn[g][lane]*S.war[128+lane] + S.hn[g][32+lane]*S.war[160+lane];
                        pa = wsum(pa);
                        if (lane == 0) S.a[g] = pa;
                    } else if (w8 == 5) {
                        float pb = S.hn[g][lane]*S.war[192+lane] + S.hn[g][32+lane]*S.war[224+lane];
                        pb = wsum(pb);
                        if (lane == 0) g_b1v[i] = pb;
                    } else if (w8 == 6 && lane == 0) {
                        float gateSum = 0.f;
#pragma unroll
                        for (int w = 0; w < 8; w++) gateSum += S.v1[g][w];
                        atomicAdd(&g_acc[0], gateSum);
                        atomicAdd(&g_acc[1], neiRow);
                        atomicAdd(&g_acc[2], maxposRow);
                        atomicAdd(&g_acc[3], neiRow > 0.f ? 1.f : 0.f);
                    }
                }
                rbar(g);
                if (mi) {
                    if (w8 == 0) {
                        float2 p0 = S.pre2[g][0][lane], p1 = S.pre2[g][1][lane];
                        ((float2*)S.A[g])[lane] = make_float2(p0.x + p1.x, p0.y + p1.y);
                    } else if (w8 == 1) {
                        float2 q0 = S.pre2[g][2][lane], q1 = S.pre2[g][3][lane];
                        ((float2*)S.gates[g])[lane] = make_float2(q0.x + q1.x, q0.y + q1.y);
                        __syncwarp();
                        g_hB1p[i*32 + lane] = make_float4(S.hn[g][lane], S.hn[g][32 + lane],
                                                          S.gates[g][lane], S.gates[g][lane + 32]);
                    }
                }
                gbar(target);
            } else {
                // outputs via 2 warp reductions
                if (w8 == 6) {
                    float o = S.hn[g][lane]*S.wout[lane] + S.hn[g][32+lane]*S.wout[32+lane];
                    o = wsum(o);
                    if (lane == 0) out[(t*NN + i)*2 + 0] = mi ? (o + S.bout[0]) : 0.f;
                } else if (w8 == 7) {
                    float o = S.hn[g][lane]*S.wout[64+lane] + S.hn[g][32+lane]*S.wout[96+lane];
                    o = wsum(o);
                    if (lane == 0) out[(t*NN + i)*2 + 1] = mi ? (o + S.bout[1]) : 0.f;
                }
            }
        }
        // no grid barrier between C and next A; groups are data-decoupled
    }

    // final writeback
    const int OFF = TT*NN*2;
    if (ltid < DH) {
        out[OFF + i*DH + ltid]         = S.h[g][ltid];
        out[OFF + NN*DH + i*DH + ltid] = S.c[g][ltid];
    }
    if (blockIdx.x == 0 && tid < 3) out[OFF + 2*NN*DH + tid] = g_v[tid] / (float)TT;
}

extern "C" void kernel_launch(void* const* d_in, const int* in_sizes, int n_in,
                              void* d_out, int out_size) {
    const float* abs_   = (const float*)d_in[0];
    const float* norm   = (const float*)d_in[1];
    const float* w_in   = (const float*)d_in[3];
    const float* b_in   = (const float*)d_in[4];
    const float* w_ih   = (const float*)d_in[5];
    const float* w_hh   = (const float*)d_in[6];
    const float* b_ih   = (const float*)d_in[7];
    const float* b_hh   = (const float*)d_in[8];
    const float* w_rel  = (const float*)d_in[9];
    const float* b_rel  = (const float*)d_in[10];
    const float* w_gate = (const float*)d_in[11];
    const float* b_gate = (const float*)d_in[12];
    const float* w_ar   = (const float*)d_in[13];
    const float* b_ar   = (const float*)d_in[14];
    const float* w_nei  = (const float*)d_in[15];
    const float* w_out  = (const float*)d_in[16];
    const float* b_out  = (const float*)d_in[17];
    const int*   seq    = (const int*)d_in[18];
    const int*   nei    = (const int*)d_in[19];
    float* out = (float*)d_out;

    cudaFuncSetAttribute(fused_kernel, cudaFuncAttributeMaxDynamicSharedMemorySize,
                         (int)sizeof(Smem));

    void* barptr = nullptr;
    cudaGetSymbolAddress(&barptr, g_bar);
    cudaMemsetAsync(barptr, 0, sizeof(unsigned), 0);

    fused_kernel<<<NB, NTH, sizeof(Smem)>>>(abs_, norm, w_in, b_in, w_ih, w_hh, b_ih, b_hh,
                                            w_rel, b_rel, w_gate, b_gate, w_ar, b_ar,
                                            w_nei, w_out, b_out, seq, nei, out);
}

// round 13
// speedup vs baseline: 2.2795x; 1.0532x over previous
#include <cuda_runtime.h>
#include <math.h>

#define NN 192
#define TT 20
#define DH 64
#define DE 32
#define DR 32
#define NB 96
#define NTH 512
#define RPB 2

// ---- device scratch (no allocations allowed) ----
__device__ float4 g_hB0p[NN*32], g_hB1p[NN*32];    // packed {h[l], h[l+32], B[l], B[l+32]}
__device__ float  g_b0v[NN], g_b1v[NN];
__device__ float  g_acc[4], g_v[3];
__device__ unsigned g_bar[1];                      // memset to 0 each launch
__device__ float g_wABT[2*2*64*64];                // [p][part][k][h] (h fastest)

struct __align__(16) Smem {
    float4 cst4[2*DR];            // {wrel_x, wrel_y, brel, war_k}
    float2 wl2[96*128];           // LSTM weights [e][pair r]
    float2 wg2[2*DR*32];          // [p][k][lane]{h,h+32}
    float2 msg2[RPB][8][32];
    float2 pre2[RPB][4][32];      // pre-GEMV partials
    float  wnei[2*64*64];         // [p][k][h]
    float  r[RPB][DR*NN];         // [k][j]
    float  war[256];
    float  bcomb[256];
    float  bg[2*DH];
    float  bar2[2];
    float  wout[2*DH];
    float  bout[2];
    float  absv[RPB][2*NN];       // per-group copy (group decoupling + prefetch target)
    float  gates[RPB][256];
    float  xh[RPB][96];
    float  pos[RPB][NN];
    float  hn[RPB][DH];
    float  A[RPB][DH];
    float  cnp[RPB][DH];
    float  a[RPB];
    float  rr[RPB][24];
    float  v1[RPB][8];
    float  h[RPB][DH], c[RPB][DH], og[RPB][DH], ctmp[RPB][DH], msgf[RPB][DH];
    int    cnt[RPB];
    unsigned char seqb[RPB][NN];  // per-group copy
    unsigned char neib[RPB][NN];
    unsigned char actb[RPB][NN];
};

// group-local barrier: 256 threads of row-group g (named barrier g+1)
__device__ __forceinline__ void rbar(int g) {
    asm volatile("bar.sync %0, %1;" :: "r"(g + 1), "r"(256) : "memory");
}

// grid barrier: monotonic counter; release-red arrive + acquire poll (CG pattern,
// no explicit membar — bar.sync + release is cumulative per the PTX memory model)
__device__ __forceinline__ void gbar(unsigned& target) {
    __syncthreads();
    if (threadIdx.x == 0) {
        target += NB;
        asm volatile("red.release.gpu.add.u32 [%0], 1;" :: "l"(g_bar) : "memory");
        unsigned v;
        do {
            asm volatile("ld.acquire.gpu.u32 %0, [%1];" : "=r"(v) : "l"(g_bar) : "memory");
        } while ((int)(v - target) < 0);
    }
    __syncthreads();
}

__device__ __forceinline__ float wsum(float v) {
#pragma unroll
    for (int o = 16; o; o >>= 1) v += __shfl_xor_sync(0xffffffffu, v, o);
    return v;
}
__device__ __forceinline__ float wmax(float v) {
#pragma unroll
    for (int o = 16; o; o >>= 1) v = fmaxf(v, __shfl_xor_sync(0xffffffffu, v, o));
    return v;
}

__global__ void __launch_bounds__(NTH, 1)
fused_kernel(const float* __restrict__ abs_, const float* __restrict__ norm,
             const float* __restrict__ w_in, const float* __restrict__ b_in,
             const float* __restrict__ w_ih, const float* __restrict__ w_hh,
             const float* __restrict__ b_ih, const float* __restrict__ b_hh,
             const float* __restrict__ w_rel, const float* __restrict__ b_rel,
             const float* __restrict__ w_gate, const float* __restrict__ b_gate,
             const float* __restrict__ w_ar, const float* __restrict__ b_ar,
             const float* __restrict__ w_nei, const float* __restrict__ w_out,
             const float* __restrict__ b_out,
             const int* __restrict__ seq, const int* __restrict__ nei,
             float* __restrict__ out)
{
    extern __shared__ char smem_raw[];
    Smem& S = *reinterpret_cast<Smem*>(smem_raw);

    const int tid  = threadIdx.x;
    const int g    = tid >> 8;            // row group 0..1
    const int ltid = tid & 255;           // 0..255 within group
    const int lane = tid & 31;
    const int w8   = (tid >> 5) & 7;      // warp within group 0..7
    const int i    = blockIdx.x * RPB + g;
    const int gtid = blockIdx.x * NTH + tid;
    unsigned target = 0;

    // ---- one-time smem constant loads ----
    for (int idx = tid; idx < 96*128; idx += NTH) {
        int e = idx >> 7, p = idx & 127;
        int r0 = 2*p, r1 = 2*p + 1;
        float v0, v1;
        if (e < DE) { v0 = w_ih[r0*DE + e];        v1 = w_ih[r1*DE + e]; }
        else        { v0 = w_hh[r0*DH + (e - DE)]; v1 = w_hh[r1*DH + (e - DE)]; }
        S.wl2[idx] = make_float2(v0, v1);
    }
    for (int idx = tid; idx < 2*DR*32; idx += NTH) {
        int p = idx >> 10, rem = idx & 1023, k = rem >> 5, l = rem & 31;
        S.wg2[idx] = make_float2(w_gate[p*DH*160 + l*160 + k],
                                 w_gate[p*DH*160 + (l+32)*160 + k]);
    }
    for (int idx = tid; idx < 2*64*64; idx += NTH) {
        int h = idx & 63, k = (idx >> 6) & 63, p = idx >> 12;
        S.wnei[idx] = w_nei[p*DH*DH + h*DH + k];
    }
    for (int idx = tid; idx < 2*DR; idx += NTH) {
        int p = idx >> 5, k = idx & 31;
        S.cst4[idx] = make_float4(w_rel[p*DR*2 + k*2 + 0], w_rel[p*DR*2 + k*2 + 1],
                                  b_rel[p*DR + k],          w_ar[p*160 + k]);
    }
    for (int idx = tid; idx < 256; idx += NTH) {
        int p = idx >> 7, part = (idx >> 6) & 1, k = idx & 63;
        S.war[idx] = w_ar[p*160 + 32 + part*64 + k];
    }
    if (tid < 256) S.bcomb[tid] = b_ih[tid] + b_hh[tid];
    if (tid < 2*DH) S.bg[tid] = b_gate[tid];
    if (tid < 128) S.wout[tid] = w_out[tid];
    if (tid < 2) { S.bar2[tid] = b_ar[tid]; S.bout[tid] = b_out[tid]; }
    if (ltid < DH) { S.h[g][ltid] = 0.f; S.c[g][ltid] = 0.f; }

    // ---- one-time global transposes + zero init ----
    for (int idx = gtid; idx < 2*2*64*64; idx += NB*NTH) {
        int h = idx & 63, k = (idx >> 6) & 63, part = (idx >> 12) & 1, p = idx >> 13;
        g_wABT[idx] = w_gate[p*DH*160 + h*160 + 32 + part*64 + k];
    }
    if (gtid < NN*2) out[(TT-1)*NN*2 + gtid] = 0.f;
    if (blockIdx.x == 0 && tid < 4) g_acc[tid] = 0.f;
    if (blockIdx.x == 0 && tid < 3) g_v[tid] = 0.f;
    gbar(target);

    for (int t = 0; t < TT-1; t++) {
        //================ Phase A: LSTM + pre0 (inputs prefetched in prior C) ====
        if (t == 0) {
            S.absv[g][ltid] = abs_[ltid];
            if (ltid < 2*NN - 256) S.absv[g][256 + ltid] = abs_[256 + ltid];
            if (ltid < NN) {
                S.seqb[g][ltid] = (unsigned char)(seq[ltid] > 0);
                S.neib[g][ltid] = (unsigned char)(nei[(size_t)i*NN + ltid] > 0);
            }
            if (ltid < DE) {
                float n0 = norm[i*2 + 0];
                float n1 = norm[i*2 + 1];
                S.xh[g][ltid] = fmaxf(n0*w_in[ltid*2+0] + n1*w_in[ltid*2+1] + b_in[ltid], 0.f);
            }
        }
        if (ltid >= 64 && ltid < 128) S.xh[g][32 + (ltid - 64)] = S.h[g][ltid - 64];
        rbar(g);
        const int mi = S.seqb[g][i];
        if (ltid < 128) {   // LSTM gates: 2 per thread, even/odd e-split for ILP
            const float2* bc2 = (const float2*)S.bcomb;
            float2 accE = bc2[ltid];
            float2 accO = make_float2(0.f, 0.f);
#pragma unroll
            for (int e = 0; e < 96; e += 2) {
                float x0 = S.xh[g][e], x1 = S.xh[g][e+1];
                float2 w0 = S.wl2[e*128 + ltid];
                float2 w1 = S.wl2[(e+1)*128 + ltid];
                accE.x += x0 * w0.x; accE.y += x0 * w0.y;
                accO.x += x1 * w1.x; accO.y += x1 * w1.y;
            }
            ((float2*)S.gates[g])[ltid] = make_float2(accE.x + accO.x, accE.y + accO.y);
        }
        rbar(g);
        if (ltid < DH) {
            int h = ltid;
            float ig = 1.f/(1.f+__expf(-S.gates[g][h]));
            float fg = 1.f/(1.f+__expf(-S.gates[g][64 + h]));
            float gg = tanhf(S.gates[g][128 + h]);
            float og = 1.f/(1.f+__expf(-S.gates[g][192 + h]));
            float c1 = fg*S.c[g][h] + ig*gg;
            float h1 = og*tanhf(c1);
            S.ctmp[g][h] = c1;
            S.og[g][h] = og;
            S.hn[g][h] = h1;
        }
        rbar(g);
        if (mi) {   // pre0 partials: 4 warps, k split in halves
            if (w8 < 4) {
                int part = w8 >> 1, khalf = w8 & 1;
                const float2* wp = (const float2*)(g_wABT + part*4096);
                float sx = 0.f, sy = 0.f;
#pragma unroll
                for (int kk = 0; kk < 32; kk++) {
                    int k = khalf*32 + kk;
                    float hk = S.hn[g][k];
                    float2 w2 = wp[k*32 + lane];
                    sx += hk*w2.x; sy += hk*w2.y;
                }
                S.pre2[g][w8][lane] = make_float2(sx, sy);
            } else if (w8 == 4) {
                float pa = S.hn[g][lane]*S.war[lane] + S.hn[g][32+lane]*S.war[32+lane];
                pa = wsum(pa);
                if (lane == 0) S.a[g] = pa;
            } else if (w8 == 5) {
                float pb = S.hn[g][lane]*S.war[64+lane] + S.hn[g][32+lane]*S.war[96+lane];
                pb = wsum(pb);
                if (lane == 0) g_b0v[i] = pb;
            }
        }
        rbar(g);
        if (mi) {
            if (w8 == 0) {
                float2 p0 = S.pre2[g][0][lane], p1 = S.pre2[g][1][lane];
                ((float2*)S.A[g])[lane] = make_float2(p0.x + p1.x, p0.y + p1.y);
            } else if (w8 == 1) {
                float2 q0 = S.pre2[g][2][lane], q1 = S.pre2[g][3][lane];
                ((float2*)S.gates[g])[lane] = make_float2(q0.x + q1.x, q0.y + q1.y);
                __syncwarp();
                g_hB0p[i*32 + lane] = make_float4(S.hn[g][lane], S.hn[g][32 + lane],
                                                  S.gates[g][lane], S.gates[g][lane + 32]);
            }
        }
        gbar(target);

        //================ Phases B (stage0) and C (stage1) ================
#pragma unroll 1
        for (int STAGE = 0; STAGE < 2; STAGE++) {
            if (STAGE == 1 && blockIdx.x == 0 && tid == 0) {
                const float eps = 1e-6f;
                g_v[0] += g_acc[0] / (g_acc[1]*(float)DH + eps);
                g_v[1] += g_acc[2] / (g_acc[3] + eps);
                g_v[2] += g_acc[1] / (float)NN;
                g_acc[0] = g_acc[1] = g_acc[2] = g_acc[3] = 0.f;
            }
            const float4* hBp = STAGE ? g_hB1p : g_hB0p;
            const float*  gbv = STAGE ? g_b1v : g_b0v;
            const float   barv = S.bar2[STAGE];
            const float   aI   = S.a[g];
            const float   ax = S.absv[g][2*i], ay = S.absv[g][2*i+1];
            const float4* cst = S.cst4 + STAGE*DR;

            if (ltid == 0) S.cnt[g] = 0;
            // scores (one j per thread) + cache r[k][j]; even/odd split for ILP
            float nf1 = 0.f, sc1 = -1e30f;
            const int j1 = ltid;
            if (mi && j1 < NN) {
                nf1 = (S.neib[g][j1] && S.seqb[g][j1]) ? 1.f : 0.f;
                float bj = __ldcg(&gbv[j1]);
                float cx = ax - S.absv[g][2*j1], cy = ay - S.absv[g][2*j1+1];
                float scE = 0.f, scO = 0.f;
#pragma unroll
                for (int k = 0; k < DR; k += 2) {
                    float4 c0 = cst[k], c1 = cst[k+1];
                    float r0 = fmaxf(fmaf(cx, c0.x, fmaf(cy, c0.y, c0.z)), 0.f);
                    float r1 = fmaxf(fmaf(cx, c1.x, fmaf(cy, c1.y, c1.z)), 0.f);
                    S.r[g][k*NN + j1] = r0;
                    S.r[g][(k+1)*NN + j1] = r1;
                    scE += r0 * c0.w;
                    scO += r1 * c1.w;
                }
                float sc = scE + scO + aI + bj + barv;
                sc1 = (nf1 > 0.f) ? sc : -1e9f;
            }
            float e1 = __expf(sc1);     // masked -> 0
            {   // merged reduction: sum(e), max(e*nf), sum(nf)
                float se = wsum(e1), mn = wmax(e1*nf1), sn = wsum(nf1);
                if (lane == 0) { S.rr[g][w8] = se; S.rr[g][8+w8] = mn; S.rr[g][16+w8] = sn; }
            }
            rbar(g);
            float ssum = 0.f, mpos = 0.f, neiRow = 0.f;
#pragma unroll
            for (int w = 0; w < 8; w++) {
                ssum += S.rr[g][w];
                mpos = fmaxf(mpos, S.rr[g][8+w]);
                neiRow += S.rr[g][16+w];
            }
            float inv = (ssum > 0.f) ? 1.f/ssum : 0.f;
            float maxposRow = mpos * inv;
            if (j1 < NN) S.pos[g][j1] = e1 * inv * nf1;
            {   // active-list compaction
                unsigned b1 = __ballot_sync(0xffffffffu, nf1 > 0.f);
                int base = 0;
                if (lane == 0 && b1) base = atomicAdd(&S.cnt[g], __popc(b1));
                base = __shfl_sync(0xffffffffu, base, 0);
                if (nf1 > 0.f)
                    S.actb[g][base + __popc(b1 & ((1u << lane) - 1u))] = (unsigned char)j1;
            }
            rbar(g);
            // ---- input prefetch for t+1 (phase C only; absv/seqb/neib dead now) ----
            if (STAGE == 1 && t + 1 < TT-1) {
                int t2 = t + 1;
                S.absv[g][ltid] = abs_[t2*2*NN + ltid];
                if (ltid < 2*NN - 256) S.absv[g][256 + ltid] = abs_[t2*2*NN + 256 + ltid];
                if (ltid < NN) {
                    S.seqb[g][ltid] = (unsigned char)(seq[t2*NN + ltid] > 0);
                    S.neib[g][ltid] =
                        (unsigned char)(nei[(size_t)t2*NN*NN + (size_t)i*NN + ltid] > 0);
                }
                if (ltid < DE) {
                    float n0 = norm[(t2*NN + i)*2 + 0];
                    float n1 = norm[(t2*NN + i)*2 + 1];
                    S.xh[g][ltid] = fmaxf(n0*w_in[ltid*2+0] + n1*w_in[ltid*2+1] + b_in[ltid], 0.f);
                }
            }
            // gate + message loop: 2 neighbors per iteration, 8 warps strided
            const float Ai0 = S.A[g][lane]      + S.bg[STAGE*DH + lane];
            const float Ai1 = S.A[g][32 + lane] + S.bg[STAGE*DH + 32 + lane];
            const float2* wg2 = S.wg2 + STAGE*DR*32;
            const float*  rS  = S.r[g];
            float msg0 = 0.f, msg1 = 0.f, v1p = 0.f;
            const int cnt = S.cnt[g];
            for (int a = 2*w8; a < cnt; a += 16) {
                int ja = S.actb[g][a];
                bool two = (a + 1) < cnt;
                int jb = two ? S.actb[g][a+1] : ja;
                float pa = S.pos[g][ja];
                float pb = two ? S.pos[g][jb] : 0.f;
                float4 HA = __ldcg(&hBp[ja*32 + lane]);
                float4 HB = __ldcg(&hBp[jb*32 + lane]);
                float a0 = Ai0 + HA.z, a1 = Ai1 + HA.w;
                float b0 = Ai0 + HB.z, b1 = Ai1 + HB.w;
#pragma unroll
                for (int k = 0; k < DR; k++) {
                    float rva = rS[k*NN + ja];
                    float rvb = rS[k*NN + jb];
                    float2 w2 = wg2[k*32 + lane];
                    a0 += rva * w2.x; a1 += rva * w2.y;
                    b0 += rvb * w2.x; b1 += rvb * w2.y;
                }
                float ga0 = 1.f/(1.f+__expf(-a0));
                float ga1 = 1.f/(1.f+__expf(-a1));
                float gb0 = 1.f/(1.f+__expf(-b0));
                float gb1 = 1.f/(1.f+__expf(-b1));
                msg0 += pa*ga0*HA.x + pb*gb0*HB.x;
                msg1 += pa*ga1*HA.y + pb*gb1*HB.y;
                v1p  += ga0 + ga1;
                if (two) v1p += gb0 + gb1;   // don't count duplicated tail neighbor
            }
            S.msg2[g][w8][lane] = make_float2(msg0, msg1);
            if (STAGE == 0) {
                v1p = wsum(v1p);
                if (lane == 0) S.v1[g][w8] = v1p;
            }
            rbar(g);
            if (ltid < DH) {
                int h = ltid;
                float v = 0.f;
#pragma unroll
                for (int w = 0; w < 8; w++)
                    v += (h < 32) ? S.msg2[g][w][h].x : S.msg2[g][w][h-32].y;
                S.msgf[g][h] = v;
            }
            rbar(g);
            // c update GEMV split across 128 threads (k in halves, even/odd ILP)
            float accPart = 0.f;
            if (ltid < 128) {
                int part = ltid >> 6, h = ltid & 63;
                const float* wn = S.wnei + STAGE*4096;
                float aE = 0.f, aO = 0.f;
#pragma unroll
                for (int kk = 0; kk < 32; kk += 2) {
                    int k = part*32 + kk;
                    aE += S.msgf[g][k]   * wn[k*64 + h];
                    aO += S.msgf[g][k+1] * wn[(k+1)*64 + h];
                }
                accPart = aE + aO;
                if (part) S.cnp[g][h] = accPart;
            }
            rbar(g);
            if (ltid < DH) {
                int h = ltid;
                float cn = S.ctmp[g][h] + accPart + S.cnp[g][h];
                float hn = S.og[g][h]*tanhf(cn);
                S.ctmp[g][h] = cn;
                S.hn[g][h] = hn;
                if (STAGE == 1 && mi) { S.h[g][h] = hn; S.c[g][h] = cn; }
            }
            rbar(g);
            if (STAGE == 0) {
                if (mi) {   // pre1 partials + stats
                    if (w8 < 4) {
                        int part = w8 >> 1, khalf = w8 & 1;
                        const float2* wp = (const float2*)(g_wABT + (2 + part)*4096);
                        float sx = 0.f, sy = 0.f;
#pragma unroll
                        for (int kk = 0; kk < 32; kk++) {
                            int k = khalf*32 + kk;
                            float hk = S.hn[g][k];
                            float2 w2 = wp[k*32 + lane];
                            sx += hk*w2.x; sy += hk*w2.y;
                        }
                        S.pre2[g][w8][lane] = make_float2(sx, sy);
                    } else if (w8 == 4) {
                        float pa = S.hn[g][lane]*S.war[128+lane] + S.hn[g][32+lane]*S.war[160+lane];
                        pa = wsum(pa);
                        if (lane == 0) S.a[g] = pa;
                    } else if (w8 == 5) {
                        float pb = S.hn[g][lane]*S.war[192+lane] + S.hn[g][32+lane]*S.war[224+lane];
                        pb = wsum(pb);
                        if (lane == 0) g_b1v[i] = pb;
                    } else if (w8 == 6 && lane == 0) {
                        float gateSum = 0.f;
#pragma unroll
                        for (int w = 0; w < 8; w++) gateSum += S.v1[g][w];
                        atomicAdd(&g_acc[0], gateSum);
                        atomicAdd(&g_acc[1], neiRow);
                        atomicAdd(&g_acc[2], maxposRow);
                        atomicAdd(&g_acc[3], neiRow > 0.f ? 1.f : 0.f);
                    }
                }
                rbar(g);
                if (mi) {
                    if (w8 == 0) {
                        float2 p0 = S.pre2[g][0][lane], p1 = S.pre2[g][1][lane];
                        ((float2*)S.A[g])[lane] = make_float2(p0.x + p1.x, p0.y + p1.y);
                    } else if (w8 == 1) {
                        float2 q0 = S.pre2[g][2][lane], q1 = S.pre2[g][3][lane];
                        ((float2*)S.gates[g])[lane] = make_float2(q0.x + q1.x, q0.y + q1.y);
                        __syncwarp();
                        g_hB1p[i*32 + lane] = make_float4(S.hn[g][lane], S.hn[g][32 + lane],
                                                          S.gates[g][lane], S.gates[g][lane + 32]);
                    }
                }
                gbar(target);
            } else {
                // outputs via 2 warp reductions
                if (w8 == 6) {
                    float o = S.hn[g][lane]*S.wout[lane] + S.hn[g][32+lane]*S.wout[32+lane];
                    o = wsum(o);
                    if (lane == 0) out[(t*NN + i)*2 + 0] = mi ? (o + S.bout[0]) : 0.f;
                } else if (w8 == 7) {
                    float o = S.hn[g][lane]*S.wout[64+lane] + S.hn[g][32+lane]*S.wout[96+lane];
                    o = wsum(o);
                    if (lane == 0) out[(t*NN + i)*2 + 1] = mi ? (o + S.bout[1]) : 0.f;
                }
            }
        }
        // no grid barrier between C and next A; groups are data-decoupled
    }

    // final writeback
    const int OFF = TT*NN*2;
    if (ltid < DH) {
        out[OFF + i*DH + ltid]         = S.h[g][ltid];
        out[OFF + NN*DH + i*DH + ltid] = S.c[g][ltid];
    }
    if (blockIdx.x == 0 && tid < 3) out[OFF + 2*NN*DH + tid] = g_v[tid] / (float)TT;
}

extern "C" void kernel_launch(void* const* d_in, const int* in_sizes, int n_in,
                              void* d_out, int out_size) {
    const float* abs_   = (const float*)d_in[0];
    const float* norm   = (const float*)d_in[1];
    const float* w_in   = (const float*)d_in[3];
    const float* b_in   = (const float*)d_in[4];
    const float* w_ih   = (const float*)d_in[5];
    const float* w_hh   = (const float*)d_in[6];
    const float* b_ih   = (const float*)d_in[7];
    const float* b_hh   = (const float*)d_in[8];
    const float* w_rel  = (const float*)d_in[9];
    const float* b_rel  = (const float*)d_in[10];
    const float* w_gate = (const float*)d_in[11];
    const float* b_gate = (const float*)d_in[12];
    const float* w_ar   = (const float*)d_in[13];
    const float* b_ar   = (const float*)d_in[14];
    const float* w_nei  = (const float*)d_in[15];
    const float* w_out  = (const float*)d_in[16];
    const float* b_out  = (const float*)d_in[17];
    const int*   seq    = (const int*)d_in[18];
    const int*   nei    = (const int*)d_in[19];
    float* out = (float*)d_out;

    cudaFuncSetAttribute(fused_kernel, cudaFuncAttributeMaxDynamicSharedMemorySize,
                         (int)sizeof(Smem));

    void* barptr = nullptr;
    cudaGetSymbolAddress(&barptr, g_bar);
    cudaMemsetAsync(barptr, 0, sizeof(unsigned), 0);

    fused_kernel<<<NB, NTH, sizeof(Smem)>>>(abs_, norm, w_in, b_in, w_ih, w_hh, b_ih, b_hh,
                                            w_rel, b_rel, w_gate, b_gate, w_ar, b_ar,
                                            w_nei, w_out, b_out, seq, nei, out);
}

// round 15
// speedup vs baseline: 2.3355x; 1.0246x over previous
#include <cuda_runtime.h>
#include <math.h>

#define NN 192
#define TT 20
#define DH 64
#define DE 32
#define DR 32
#define NB 96
#define NTH 512
#define RPB 2

// ---- device scratch (no allocations allowed) ----
__device__ float4 g_hB0p[NN*32], g_hB1p[NN*32];    // packed {h[l], h[l+32], B[l], B[l+32]}
__device__ float  g_b0v[NN], g_b1v[NN];
__device__ float  g_acc[4], g_v[3];
__device__ unsigned g_bar[1];                      // memset to 0 each launch
__device__ float g_wABT[2*2*64*64];                // [p][part][k][h] (h fastest)

struct __align__(16) Smem {
    float4 cst4[2*DR];            // {wrel_x, wrel_y, brel, war_k}
    float4 wg4[2*16*32];          // [p][kpair][lane]{w2k[h],w2k[h+32],w2k1[h],w2k1[h+32]}
    float2 wl2[96*128];           // LSTM weights [e][pair r]
    float2 r2[RPB][16*NN];        // [kpair][j] {r[2k],r[2k+1]}
    float2 msg2[RPB][8][32];
    float2 pre2[RPB][4][32];      // pre-GEMV partials
    float  wnei[2*64*64];         // [p][k][h]
    float  war[256];
    float  bcomb[256];
    float  bg[2*DH];
    float  bar2[2];
    float  wout[2*DH];
    float  bout[2];
    float  absv[RPB][2*NN];       // per-group copy (group decoupling + prefetch target)
    float  gates[RPB][256];
    float  xh[RPB][96];
    float  pos[RPB][NN];          // UNNORMALIZED e*nf
    float  hn[RPB][DH];
    float  A[RPB][DH];
    float  a[RPB];
    float  rr[RPB][24];
    float  v1[RPB][8];
    float  h[RPB][DH], c[RPB][DH], og[RPB][DH], ctmp[RPB][DH], msgf[RPB][DH];
    int    cnt[RPB];
    unsigned char seqb[RPB][NN];  // per-group copy
    unsigned char neib[RPB][NN];
    unsigned char actb[RPB][NN];
};

// group-local barrier: 256 threads of row-group g (named barrier g+1)
__device__ __forceinline__ void rbar(int g) {
    asm volatile("bar.sync %0, %1;" :: "r"(g + 1), "r"(256) : "memory");
}

// grid barrier: monotonic counter; release-red arrive + acquire poll
__device__ __forceinline__ void gbar(unsigned& target) {
    __syncthreads();
    if (threadIdx.x == 0) {
        target += NB;
        asm volatile("red.release.gpu.add.u32 [%0], 1;" :: "l"(g_bar) : "memory");
        unsigned v;
        do {
            asm volatile("ld.acquire.gpu.u32 %0, [%1];" : "=r"(v) : "l"(g_bar) : "memory");
        } while ((int)(v - target) < 0);
    }
    __syncthreads();
}

__device__ __forceinline__ float wsum(float v) {
#pragma unroll
    for (int o = 16; o; o >>= 1) v += __shfl_xor_sync(0xffffffffu, v, o);
    return v;
}
__device__ __forceinline__ float wmax(float v) {
#pragma unroll
    for (int o = 16; o; o >>= 1) v = fmaxf(v, __shfl_xor_sync(0xffffffffu, v, o));
    return v;
}

__global__ void __launch_bounds__(NTH, 1)
fused_kernel(const float* __restrict__ abs_, const float* __restrict__ norm,
             const float* __restrict__ w_in, const float* __restrict__ b_in,
             const float* __restrict__ w_ih, const float* __restrict__ w_hh,
             const float* __restrict__ b_ih, const float* __restrict__ b_hh,
             const float* __restrict__ w_rel, const float* __restrict__ b_rel,
             const float* __restrict__ w_gate, const float* __restrict__ b_gate,
             const float* __restrict__ w_ar, const float* __restrict__ b_ar,
             const float* __restrict__ w_nei, const float* __restrict__ w_out,
             const float* __restrict__ b_out,
             const int* __restrict__ seq, const int* __restrict__ nei,
             float* __restrict__ out)
{
    extern __shared__ char smem_raw[];
    Smem& S = *reinterpret_cast<Smem*>(smem_raw);

    const int tid  = threadIdx.x;
    const int g    = tid >> 8;            // row group 0..1
    const int ltid = tid & 255;           // 0..255 within group
    const int lane = tid & 31;
    const int w8   = (tid >> 5) & 7;      // warp within group 0..7
    const int i    = blockIdx.x * RPB + g;
    const int gtid = blockIdx.x * NTH + tid;
    unsigned target = 0;

    // ---- one-time smem constant loads ----
    for (int idx = tid; idx < 96*128; idx += NTH) {
        int e = idx >> 7, p = idx & 127;
        int r0 = 2*p, r1 = 2*p + 1;
        float v0, v1;
        if (e < DE) { v0 = w_ih[r0*DE + e];        v1 = w_ih[r1*DE + e]; }
        else        { v0 = w_hh[r0*DH + (e - DE)]; v1 = w_hh[r1*DH + (e - DE)]; }
        S.wl2[idx] = make_float2(v0, v1);
    }
    for (int idx = tid; idx < 2*16*32; idx += NTH) {
        int p = idx >> 9, rem = idx & 511, kp = rem >> 5, l = rem & 31;
        const float* wp = w_gate + p*DH*160;
        S.wg4[idx] = make_float4(wp[l*160 + 2*kp],      wp[(l+32)*160 + 2*kp],
                                 wp[l*160 + 2*kp + 1],  wp[(l+32)*160 + 2*kp + 1]);
    }
    for (int idx = tid; idx < 2*64*64; idx += NTH) {
        int h = idx & 63, k = (idx >> 6) & 63, p = idx >> 12;
        S.wnei[idx] = w_nei[p*DH*DH + h*DH + k];
    }
    for (int idx = tid; idx < 2*DR; idx += NTH) {
        int p = idx >> 5, k = idx & 31;
        S.cst4[idx] = make_float4(w_rel[p*DR*2 + k*2 + 0], w_rel[p*DR*2 + k*2 + 1],
                                  b_rel[p*DR + k],          w_ar[p*160 + k]);
    }
    for (int idx = tid; idx < 256; idx += NTH) {
        int p = idx >> 7, part = (idx >> 6) & 1, k = idx & 63;
        S.war[idx] = w_ar[p*160 + 32 + part*64 + k];
    }
    if (tid < 256) S.bcomb[tid] = b_ih[tid] + b_hh[tid];
    if (tid < 2*DH) S.bg[tid] = b_gate[tid];
    if (tid < 128) S.wout[tid] = w_out[tid];
    if (tid < 2) { S.bar2[tid] = b_ar[tid]; S.bout[tid] = b_out[tid]; }
    if (ltid < DH) { S.h[g][ltid] = 0.f; S.c[g][ltid] = 0.f; }
    if (ltid == 0) S.cnt[g] = 0;

    // ---- one-time global transposes + zero init ----
    for (int idx = gtid; idx < 2*2*64*64; idx += NB*NTH) {
        int h = idx & 63, k = (idx >> 6) & 63, part = (idx >> 12) & 1, p = idx >> 13;
        g_wABT[idx] = w_gate[p*DH*160 + h*160 + 32 + part*64 + k];
    }
    if (gtid < NN*2) out[(TT-1)*NN*2 + gtid] = 0.f;
    if (blockIdx.x == 0 && tid < 4) g_acc[tid] = 0.f;
    if (blockIdx.x == 0 && tid < 3) g_v[tid] = 0.f;
    gbar(target);

    for (int t = 0; t < TT-1; t++) {
        //================ Phase A: LSTM + pre0 (inputs prefetched in prior C) ====
        if (t == 0) {
            S.absv[g][ltid] = abs_[ltid];
            if (ltid < 2*NN - 256) S.absv[g][256 + ltid] = abs_[256 + ltid];
            if (ltid < NN) {
                S.seqb[g][ltid] = (unsigned char)(seq[ltid] > 0);
                S.neib[g][ltid] = (unsigned char)(nei[(size_t)i*NN + ltid] > 0);
            }
            if (ltid < DE) {
                float n0 = norm[i*2 + 0];
                float n1 = norm[i*2 + 1];
                S.xh[g][ltid] = fmaxf(n0*w_in[ltid*2+0] + n1*w_in[ltid*2+1] + b_in[ltid], 0.f);
            }
        }
        if (ltid >= 64 && ltid < 128) S.xh[g][32 + (ltid - 64)] = S.h[g][ltid - 64];
        rbar(g);
        const int mi = S.seqb[g][i];
        if (ltid < 128) {   // LSTM gates: 2 per thread, even/odd e-split for ILP
            const float2* bc2 = (const float2*)S.bcomb;
            float2 accE = bc2[ltid];
            float2 accO = make_float2(0.f, 0.f);
#pragma unroll
            for (int e = 0; e < 96; e += 2) {
                float x0 = S.xh[g][e], x1 = S.xh[g][e+1];
                float2 w0 = S.wl2[e*128 + ltid];
                float2 w1 = S.wl2[(e+1)*128 + ltid];
                accE.x += x0 * w0.x; accE.y += x0 * w0.y;
                accO.x += x1 * w1.x; accO.y += x1 * w1.y;
            }
            ((float2*)S.gates[g])[ltid] = make_float2(accE.x + accO.x, accE.y + accO.y);
        }
        rbar(g);
        if (ltid < DH) {
            int h = ltid;
            float ig = 1.f/(1.f+__expf(-S.gates[g][h]));
            float fg = 1.f/(1.f+__expf(-S.gates[g][64 + h]));
            float gg = tanhf(S.gates[g][128 + h]);
            float og = 1.f/(1.f+__expf(-S.gates[g][192 + h]));
            float c1 = fg*S.c[g][h] + ig*gg;
            float h1 = og*tanhf(c1);
            S.ctmp[g][h] = c1;
            S.og[g][h] = og;
            S.hn[g][h] = h1;
        }
        rbar(g);
        if (mi) {   // pre0 partials: 4 warps, k split in halves
            if (w8 < 4) {
                int part = w8 >> 1, khalf = w8 & 1;
                const float2* wp = (const float2*)(g_wABT + part*4096);
                float sx = 0.f, sy = 0.f;
#pragma unroll
                for (int kk = 0; kk < 32; kk++) {
                    int k = khalf*32 + kk;
                    float hk = S.hn[g][k];
                    float2 w2 = wp[k*32 + lane];
                    sx += hk*w2.x; sy += hk*w2.y;
                }
                S.pre2[g][w8][lane] = make_float2(sx, sy);
            } else if (w8 == 4) {
                float pa = S.hn[g][lane]*S.war[lane] + S.hn[g][32+lane]*S.war[32+lane];
                pa = wsum(pa);
                if (lane == 0) S.a[g] = pa;
            } else if (w8 == 5) {
                float pb = S.hn[g][lane]*S.war[64+lane] + S.hn[g][32+lane]*S.war[96+lane];
                pb = wsum(pb);
                if (lane == 0) g_b0v[i] = pb;
            }
        }
        rbar(g);
        if (mi) {
            if (w8 == 0) {
                float2 p0 = S.pre2[g][0][lane], p1 = S.pre2[g][1][lane];
                ((float2*)S.A[g])[lane] = make_float2(p0.x + p1.x, p0.y + p1.y);
            } else if (w8 == 1) {
                // pair-packed {B[2l],B[2l+1]} -> smem -> strided re-read {B[l],B[l+32]}
                float2 q0 = S.pre2[g][2][lane], q1 = S.pre2[g][3][lane];
                ((float2*)S.gates[g])[lane] = make_float2(q0.x + q1.x, q0.y + q1.y);
                __syncwarp();
                g_hB0p[i*32 + lane] = make_float4(S.hn[g][lane], S.hn[g][32 + lane],
                                                  S.gates[g][lane], S.gates[g][lane + 32]);
            }
        }
        gbar(target);

        //================ Phases B (stage0) and C (stage1) ================
#pragma unroll 1
        for (int STAGE = 0; STAGE < 2; STAGE++) {
            if (STAGE == 1 && blockIdx.x == 0 && tid == 0) {
                const float eps = 1e-6f;
                g_v[0] += g_acc[0] / (g_acc[1]*(float)DH + eps);
                g_v[1] += g_acc[2] / (g_acc[3] + eps);
                g_v[2] += g_acc[1] / (float)NN;
                g_acc[0] = g_acc[1] = g_acc[2] = g_acc[3] = 0.f;
            }
            const float4* hBp = STAGE ? g_hB1p : g_hB0p;
            const float*  gbv = STAGE ? g_b1v : g_b0v;
            const float   barv = S.bar2[STAGE];
            const float   aI   = S.a[g];
            const float   ax = S.absv[g][2*i], ay = S.absv[g][2*i+1];
            const float4* cst = S.cst4 + STAGE*DR;

            // ---- score stage: scores + r2 cache + pos(e*nf) + compaction + reductions
            float nf1 = 0.f, sc1 = -1e30f;
            const int j1 = ltid;
            if (mi && j1 < NN) {
                nf1 = (S.neib[g][j1] && S.seqb[g][j1]) ? 1.f : 0.f;
                float bj = __ldcg(&gbv[j1]);
                float cx = ax - S.absv[g][2*j1], cy = ay - S.absv[g][2*j1+1];
                float scE = 0.f, scO = 0.f;
#pragma unroll
                for (int kp = 0; kp < 16; kp++) {
                    float4 c0 = cst[2*kp], c1 = cst[2*kp+1];
                    float r0 = fmaxf(fmaf(cx, c0.x, fmaf(cy, c0.y, c0.z)), 0.f);
                    float r1 = fmaxf(fmaf(cx, c1.x, fmaf(cy, c1.y, c1.z)), 0.f);
                    S.r2[g][kp*NN + j1] = make_float2(r0, r1);
                    scE += r0 * c0.w;
                    scO += r1 * c1.w;
                }
                float sc = scE + scO + aI + bj + barv;
                sc1 = (nf1 > 0.f) ? sc : -1e9f;
            }
            float e1 = __expf(sc1);     // masked -> 0
            if (j1 < NN) S.pos[g][j1] = e1 * nf1;   // UNNORMALIZED
            {   // compaction (needs only nf1; cnt was reset last stage under barrier)
                unsigned b1 = __ballot_sync(0xffffffffu, nf1 > 0.f);
                int base = 0;
                if (lane == 0 && b1) base = atomicAdd(&S.cnt[g], __popc(b1));
                base = __shfl_sync(0xffffffffu, base, 0);
                if (nf1 > 0.f)
                    S.actb[g][base + __popc(b1 & ((1u << lane) - 1u))] = (unsigned char)j1;
            }
            {   // merged reduction: sum(e), max(e*nf), sum(nf)
                float se = wsum(e1), mn = wmax(e1*nf1), sn = wsum(nf1);
                if (lane == 0) { S.rr[g][w8] = se; S.rr[g][8+w8] = mn; S.rr[g][16+w8] = sn; }
            }
            rbar(g);
            float ssum = 0.f, mpos = 0.f, neiRow = 0.f;
#pragma unroll
            for (int w = 0; w < 8; w++) {
                ssum += S.rr[g][w];
                mpos = fmaxf(mpos, S.rr[g][8+w]);
                neiRow += S.rr[g][16+w];
            }
            const float inv = (ssum > 0.f) ? 1.f/ssum : 0.f;
            const float maxposRow = mpos * inv;
            // ---- input prefetch for t+1 (stage1 only; absv/seqb/neib/xh dead now) ----
            if (STAGE == 1 && t + 1 < TT-1) {
                int t2 = t + 1;
                S.absv[g][ltid] = abs_[t2*2*NN + ltid];
                if (ltid < 2*NN - 256) S.absv[g][256 + ltid] = abs_[t2*2*NN + 256 + ltid];
                if (ltid < NN) {
                    S.seqb[g][ltid] = (unsigned char)(seq[t2*NN + ltid] > 0);
                    S.neib[g][ltid] =
                        (unsigned char)(nei[(size_t)t2*NN*NN + (size_t)i*NN + ltid] > 0);
                }
                if (ltid < DE) {
                    float n0 = norm[(t2*NN + i)*2 + 0];
                    float n1 = norm[(t2*NN + i)*2 + 1];
                    S.xh[g][ltid] = fmaxf(n0*w_in[ltid*2+0] + n1*w_in[ltid*2+1] + b_in[ltid], 0.f);
                }
            }
            // ---- gate + message loop: 2 neighbors/iter, 8 warps strided ----
            const float Ai0 = S.A[g][lane]      + S.bg[STAGE*DH + lane];
            const float Ai1 = S.A[g][32 + lane] + S.bg[STAGE*DH + 32 + lane];
            const float4* wg4 = S.wg4 + STAGE*16*32;
            const float2* rS2 = S.r2[g];
            float msg0 = 0.f, msg1 = 0.f, v1p = 0.f;
            const int cnt = S.cnt[g];
            for (int a = 2*w8; a < cnt; a += 16) {
                int ja = S.actb[g][a];
                bool two = (a + 1) < cnt;
                int jb = two ? S.actb[g][a+1] : ja;
                float pa = S.pos[g][ja] * inv;
                float pb = two ? S.pos[g][jb] * inv : 0.f;
                float4 HA = __ldcg(&hBp[ja*32 + lane]);   // issued early,
                float4 HB = __ldcg(&hBp[jb*32 + lane]);   // consumed after k-loop
                float a0 = Ai0, a1 = Ai1, b0 = Ai0, b1 = Ai1;
#pragma unroll
                for (int kp = 0; kp < 16; kp++) {
                    float2 ra = rS2[kp*NN + ja];
                    float2 rb = rS2[kp*NN + jb];
                    float4 w4 = wg4[kp*32 + lane];
                    a0 += ra.x*w4.x + ra.y*w4.z;
                    a1 += ra.x*w4.y + ra.y*w4.w;
                    b0 += rb.x*w4.x + rb.y*w4.z;
                    b1 += rb.x*w4.y + rb.y*w4.w;
                }
                a0 += HA.z; a1 += HA.w;
                b0 += HB.z; b1 += HB.w;
                float ga0 = 1.f/(1.f+__expf(-a0));
                float ga1 = 1.f/(1.f+__expf(-a1));
                float gb0 = 1.f/(1.f+__expf(-b0));
                float gb1 = 1.f/(1.f+__expf(-b1));
                msg0 += pa*ga0*HA.x + pb*gb0*HB.x;
                msg1 += pa*ga1*HA.y + pb*gb1*HB.y;
                v1p  += ga0 + ga1;
                if (two) v1p += gb0 + gb1;   // don't count duplicated tail neighbor
            }
            S.msg2[g][w8][lane] = make_float2(msg0, msg1);
            if (STAGE == 0) {
                v1p = wsum(v1p);
                if (lane == 0) S.v1[g][w8] = v1p;
            }
            rbar(g);
            if (ltid < DH) {
                int h = ltid;
                float v = 0.f;
#pragma unroll
                for (int w = 0; w < 8; w++)
                    v += (h < 32) ? S.msg2[g][w][h].x : S.msg2[g][w][h-32].y;
                S.msgf[g][h] = v;
            }
            if (ltid == 128) S.cnt[g] = 0;   // safe: all gate-loop reads done (rbar above)
            rbar(g);
            // ---- merged cn GEMV + hn update (64 threads, 4 accumulators) ----
            if (ltid < DH) {
                int h = ltid;
                float cn = S.ctmp[g][h];
                float hn = S.hn[g][h];
                if (cnt) {
                    const float* wn = S.wnei + STAGE*4096;
                    float q0 = 0.f, q1 = 0.f, q2 = 0.f, q3 = 0.f;
#pragma unroll
                    for (int k = 0; k < 64; k += 4) {
                        q0 += S.msgf[g][k]   * wn[k*64 + h];
                        q1 += S.msgf[g][k+1] * wn[(k+1)*64 + h];
                        q2 += S.msgf[g][k+2] * wn[(k+2)*64 + h];
                        q3 += S.msgf[g][k+3] * wn[(k+3)*64 + h];
                    }
                    cn += (q0 + q1) + (q2 + q3);
                    hn = S.og[g][h]*tanhf(cn);
                }
                S.ctmp[g][h] = cn;
                S.hn[g][h] = hn;
                if (STAGE == 1 && mi) { S.h[g][h] = hn; S.c[g][h] = cn; }
            }
            rbar(g);
            if (STAGE == 0) {
                if (mi) {   // pre1 partials + stats
                    if (w8 < 4) {
                        int part = w8 >> 1, khalf = w8 & 1;
                        const float2* wp = (const float2*)(g_wABT + (2 + part)*4096);
                        float sx = 0.f, sy = 0.f;
#pragma unroll
                        for (int kk = 0; kk < 32; kk++) {
                            int k = khalf*32 + kk;
                            float hk = S.hn[g][k];
                            float2 w2 = wp[k*32 + lane];
                            sx += hk*w2.x; sy += hk*w2.y;
                        }
                        S.pre2[g][w8][lane] = make_float2(sx, sy);
                    } else if (w8 == 4) {
                        float pa = S.hn[g][lane]*S.war[128+lane] + S.hn[g][32+lane]*S.war[160+lane];
                        pa = wsum(pa);
                        if (lane == 0) S.a[g] = pa;
                    } else if (w8 == 5) {
                        float pb = S.hn[g][lane]*S.war[192+lane] + S.hn[g][32+lane]*S.war[224+lane];
                        pb = wsum(pb);
                        if (lane == 0) g_b1v[i] = pb;
                    } else if (w8 == 6 && lane == 0) {
                        float gateSum = 0.f;
#pragma unroll
                        for (int w = 0; w < 8; w++) gateSum += S.v1[g][w];
                        atomicAdd(&g_acc[0], gateSum);
                        atomicAdd(&g_acc[1], neiRow);
                        atomicAdd(&g_acc[2], maxposRow);
                        atomicAdd(&g_acc[3], neiRow > 0.f ? 1.f : 0.f);
                    }
                }
                rbar(g);
                if (mi) {
                    if (w8 == 0) {
                        float2 p0 = S.pre2[g][0][lane], p1 = S.pre2[g][1][lane];
                        ((float2*)S.A[g])[lane] = make_float2(p0.x + p1.x, p0.y + p1.y);
                    } else if (w8 == 1) {
                        // pair-packed -> smem -> strided re-read {B[l],B[l+32]}
                        float2 q0 = S.pre2[g][2][lane], q1 = S.pre2[g][3][lane];
                        ((float2*)S.gates[g])[lane] = make_float2(q0.x + q1.x, q0.y + q1.y);
                        __syncwarp();
                        g_hB1p[i*32 + lane] = make_float4(S.hn[g][lane], S.hn[g][32 + lane],
                                                          S.gates[g][lane], S.gates[g][lane + 32]);
                    }
                }
                gbar(target);
            } else {
                // outputs via 2 warp reductions
                if (w8 == 6) {
                    float o = S.hn[g][lane]*S.wout[lane] + S.hn[g][32+lane]*S.wout[32+lane];
                    o = wsum(o);
                    if (lane == 0) out[(t*NN + i)*2 + 0] = mi ? (o + S.bout[0]) : 0.f;
                } else if (w8 == 7) {
                    float o = S.hn[g][lane]*S.wout[64+lane] + S.hn[g][32+lane]*S.wout[96+lane];
                    o = wsum(o);
                    if (lane == 0) out[(t*NN + i)*2 + 1] = mi ? (o + S.bout[1]) : 0.f;
                }
            }
        }
        // no grid barrier between C and next A; groups are data-decoupled
    }

    // final writeback
    const int OFF = TT*NN*2;
    if (ltid < DH) {
        out[OFF + i*DH + ltid]         = S.h[g][ltid];
        out[OFF + NN*DH + i*DH + ltid] = S.c[g][ltid];
    }
    if (blockIdx.x == 0 && tid < 3) out[OFF + 2*NN*DH + tid] = g_v[tid] / (float)TT;
}

extern "C" void kernel_launch(void* const* d_in, const int* in_sizes, int n_in,
                              void* d_out, int out_size) {
    const float* abs_   = (const float*)d_in[0];
    const float* norm   = (const float*)d_in[1];
    const float* w_in   = (const float*)d_in[3];
    const float* b_in   = (const float*)d_in[4];
    const float* w_ih   = (const float*)d_in[5];
    const float* w_hh   = (const float*)d_in[6];
    const float* b_ih   = (const float*)d_in[7];
    const float* b_hh   = (const float*)d_in[8];
    const float* w_rel  = (const float*)d_in[9];
    const float* b_rel  = (const float*)d_in[10];
    const float* w_gate = (const float*)d_in[11];
    const float* b_gate = (const float*)d_in[12];
    const float* w_ar   = (const float*)d_in[13];
    const float* b_ar   = (const float*)d_in[14];
    const float* w_nei  = (const float*)d_in[15];
    const float* w_out  = (const float*)d_in[16];
    const float* b_out  = (const float*)d_in[17];
    const int*   seq    = (const int*)d_in[18];
    const int*   nei    = (const int*)d_in[19];
    float* out = (float*)d_out;

    cudaFuncSetAttribute(fused_kernel, cudaFuncAttributeMaxDynamicSharedMemorySize,
                         (int)sizeof(Smem));

    void* barptr = nullptr;
    cudaGetSymbolAddress(&barptr, g_bar);
    cudaMemsetAsync(barptr, 0, sizeof(unsigned), 0);

    fused_kernel<<<NB, NTH, sizeof(Smem)>>>(abs_, norm, w_in, b_in, w_ih, w_hh, b_ih, b_hh,
                                            w_rel, b_rel, w_gate, b_gate, w_ar, b_ar,
                                            w_nei, w_out, b_out, seq, nei, out);
}